// round 9
// baseline (speedup 1.0000x reference)
#include <cuda_runtime.h>
#include <math.h>
#include <stdint.h>

// ---------------------------------------------------------------------------
// SwitchHeadCore: B=2,S=2048,D=1024,H=8,E=4,K=2,DH=128
// Pre-converted tf32 operands; 512-thread cp.async GEMMs (16 warps);
// 512-thread flash attention (16 warps, warp-pair split softmax).
// ---------------------------------------------------------------------------

#define B_ 2
#define S_ 2048
#define D_ 1024
#define H_ 8
#define E_ 4
#define DH_ 128
#define TOK_ (B_ * S_)              // 4096
#define GE_ (H_ * E_)               // 32
#define KEXP_ 4096                  // H*E*DH

__device__ __align__(16) float g_q[TOK_ * D_];     // [B,H,S,DH] tf32 bits
__device__ __align__(16) float g_k[TOK_ * D_];     // tf32 bits
__device__ __align__(16) float g_v[TOK_ * D_];     // tf32 bits
__device__ __align__(16) float g_res[TOK_ * D_];   // fp32
__device__ float g_gv[TOK_ * GE_];
__device__ float g_go[TOK_ * GE_];
__device__ __align__(16) float g_yall[(size_t)TOK_ * KEXP_];  // fp32
__device__ __align__(16) float g_aexp[(size_t)TOK_ * KEXP_];  // tf32 bits
__device__ __align__(16) float g_wvT[(size_t)KEXP_ * D_];     // tf32 bits
__device__ __align__(16) float g_woT[(size_t)D_ * KEXP_];     // tf32 bits
__device__ __align__(16) float g_qc[TOK_ * D_];    // tf32 of q_src
__device__ __align__(16) float g_kc[TOK_ * D_];    // tf32 of k_src
__device__ __align__(16) float g_vc[TOK_ * D_];    // tf32 of v_src
__device__ __align__(16) float g_wqc[D_ * D_];     // tf32 of Wq
__device__ __align__(16) float g_wkc[D_ * D_];     // tf32 of Wk

// ============================ helpers ======================================
__device__ __forceinline__ uint32_t f2tf32(float f) {
    uint32_t u;
    asm("cvt.rna.tf32.f32 %0, %1;" : "=r"(u) : "f"(f));
    return u;
}
__device__ __forceinline__ float f2tf32f(float f) { return __uint_as_float(f2tf32(f)); }
__device__ __forceinline__ void mma_tf32(float* d, const uint32_t* a, const uint32_t* b) {
    asm volatile(
        "mma.sync.aligned.m16n8k8.row.col.f32.tf32.tf32.f32 "
        "{%0,%1,%2,%3}, {%4,%5,%6,%7}, {%8,%9}, {%0,%1,%2,%3};\n"
        : "+f"(d[0]), "+f"(d[1]), "+f"(d[2]), "+f"(d[3])
        : "r"(a[0]), "r"(a[1]), "r"(a[2]), "r"(a[3]), "r"(b[0]), "r"(b[1]));
}
__device__ __forceinline__ uint32_t smem_u32(const void* p) {
    uint32_t a;
    asm("{ .reg .u64 t; cvta.to.shared.u64 t, %1; cvt.u32.u64 %0, t; }" : "=r"(a) : "l"(p));
    return a;
}
#define CP16(dst, src) \
    asm volatile("cp.async.cg.shared.global [%0], [%1], 16;" :: "r"(dst), "l"(src))
#define CP_COMMIT() asm volatile("cp.async.commit_group;")
#define CP_WAIT1() asm volatile("cp.async.wait_group 1;")
#define CP_WAIT0() asm volatile("cp.async.wait_group 0;")

// ============================ router =======================================
__global__ void router_kernel(const float* __restrict__ q_src,
                              const float* __restrict__ k_src,
                              const float* __restrict__ sel_v,
                              const float* __restrict__ sel_o) {
    int t = blockIdx.x;
    int tid = threadIdx.x;
    __shared__ float xs[D_];
    __shared__ float sg[GE_];

    for (int r = 0; r < 2; r++) {
        const float* src = (r == 0) ? k_src : q_src;
        const float* sel = (r == 0) ? sel_v : sel_o;
        float* gout      = (r == 0) ? g_gv  : g_go;

        for (int i = tid; i < D_ / 4; i += blockDim.x)
            ((float4*)xs)[i] = ((const float4*)(src + (size_t)t * D_))[i];
        __syncthreads();

        int g = tid >> 3;
        int l8 = tid & 7;
        const float* w = sel + (size_t)g * D_;
        float sum = 0.f;
        for (int d = l8; d < D_; d += 8) sum += xs[d] * w[d];
        sum += __shfl_xor_sync(0xffffffffu, sum, 1);
        sum += __shfl_xor_sync(0xffffffffu, sum, 2);
        sum += __shfl_xor_sync(0xffffffffu, sum, 4);
        if (l8 == 0) sg[g] = 1.f / (1.f + __expf(-sum));
        __syncthreads();

        if (tid < H_) {
            int h = tid;
            float vals[4];
            #pragma unroll
            for (int e = 0; e < 4; e++) vals[e] = sg[h * 4 + e];
            int i1 = 0;
            #pragma unroll
            for (int e = 1; e < 4; e++) if (vals[e] > vals[i1]) i1 = e;
            int i2 = -1;
            #pragma unroll
            for (int e = 0; e < 4; e++) {
                if (e == i1) continue;
                if (i2 < 0 || vals[e] > vals[i2]) i2 = e;
            }
            #pragma unroll
            for (int e = 0; e < 4; e++)
                gout[(size_t)t * GE_ + h * 4 + e] = (e == i1 || e == i2) ? vals[e] : 0.f;
        }
        __syncthreads();
    }
}

// ============================ convert (fp32 -> tf32 bits) ==================
__global__ void conv_kernel(const float* __restrict__ src, float* __restrict__ dst, int n4) {
    int i = blockIdx.x * blockDim.x + threadIdx.x;
    if (i >= n4) return;
    float4 v = ((const float4*)src)[i];
    v.x = f2tf32f(v.x); v.y = f2tf32f(v.y); v.z = f2tf32f(v.z); v.w = f2tf32f(v.w);
    ((float4*)dst)[i] = v;
}

// ============================ transpose (emit tf32) ========================
__global__ void transpose_kernel(const float* __restrict__ src, float* __restrict__ dst,
                                 int R, int C) {
    __shared__ float tile[32][33];
    size_t zo = (size_t)blockIdx.z * R * C;
    src += zo; dst += zo;
    int r0 = blockIdx.y * 32, c0 = blockIdx.x * 32;
    int x = threadIdx.x, y = threadIdx.y;
    #pragma unroll
    for (int i = 0; i < 32; i += 8)
        tile[y + i][x] = src[(size_t)(r0 + y + i) * C + c0 + x];
    __syncthreads();
    #pragma unroll
    for (int i = 0; i < 32; i += 8)
        dst[(size_t)(c0 + y + i) * R + r0 + x] = f2tf32f(tile[x][y + i]);
}

// ============================ gated expand (O), tf32 out ===================
__global__ __launch_bounds__(256) void expand_kernel() {
    int idx = blockIdx.x * 256 + threadIdx.x;   // 4096*32*32
    int dh4 = idx & 31;
    int he = (idx >> 5) & 31;
    int t = idx >> 10;
    int h = he >> 2;
    int b = t >> 11, s = t & (S_ - 1);
    float g = g_go[(size_t)t * GE_ + he];
    float4 r = *(const float4*)&g_res[(((size_t)b * H_ + h) * S_ + s) * DH_ + dh4 * 4];
    r.x = f2tf32f(r.x * g); r.y = f2tf32f(r.y * g);
    r.z = f2tf32f(r.z * g); r.w = f2tf32f(r.w * g);
    *(float4*)&g_aexp[(size_t)t * KEXP_ + he * 128 + dh4 * 4] = r;
}

// ============================ gated reduce (V), tf32 out ===================
__global__ __launch_bounds__(256) void vgate_kernel() {
    int idx = blockIdx.x * 256 + threadIdx.x;   // 4096*8*32
    int dh4 = idx & 31;
    int h = (idx >> 5) & 7;
    int t = idx >> 8;
    int b = t >> 11, s = t & (S_ - 1);
    const float* y = g_yall + (size_t)t * KEXP_ + h * 512 + dh4 * 4;
    const float* g = g_gv + (size_t)t * GE_ + h * 4;
    float4 acc = make_float4(0.f, 0.f, 0.f, 0.f);
    #pragma unroll
    for (int e = 0; e < 4; e++) {
        float ge = g[e];
        float4 ye = *(const float4*)(y + e * 128);
        acc.x += ge * ye.x; acc.y += ge * ye.y; acc.z += ge * ye.z; acc.w += ge * ye.w;
    }
    acc.x = f2tf32f(acc.x); acc.y = f2tf32f(acc.y);
    acc.z = f2tf32f(acc.z); acc.w = f2tf32f(acc.w);
    *(float4*)&g_v[(((size_t)b * H_ + h) * S_ + s) * DH_ + dh4 * 4] = acc;
}

// ============================ tf32 mma GEMM (cp.async, 512 thr) ============
#define PAD_ 36
#define ABUF_ (128 * PAD_)
#define BBUF_ (256 * PAD_)
#define STG_W (ABUF_ + BBUF_)
#define GSMEM_BYTES (3 * STG_W * 4)     // 165888

template<int MODE>
__global__ __launch_bounds__(512) void gemm_tf32(const float* __restrict__ A,
                                                 const float* __restrict__ B,
                                                 float* __restrict__ C,
                                                 int Ktot, int ldc, float alpha,
                                                 const float* __restrict__ A2,
                                                 const float* __restrict__ B2,
                                                 float* __restrict__ C2) {
    extern __shared__ __align__(16) uint32_t dsm[];
    uint32_t sbase = smem_u32(dsm);

    int tid = threadIdx.x;
    int wid = tid >> 5;
    int lane = tid & 31;
    int m0 = blockIdx.y * 128, n0 = blockIdx.x * 256;
    int m0w = (wid >> 2) * 32, n0w = (wid & 3) * 64;

    if (MODE == 1 && blockIdx.z == 1) { A = A2; B = B2; C = C2; }

    int aS0 = tid, aS1 = tid + 512;
    int ar0 = aS0 >> 3, ac0 = (aS0 & 7) * 4;
    int ar1 = aS1 >> 3, ac1 = (aS1 & 7) * 4;
    const float* Asrc0 = A + (size_t)(m0 + ar0) * Ktot + ac0;
    const float* Asrc1 = A + (size_t)(m0 + ar1) * Ktot + ac1;
    uint32_t aDst0 = (uint32_t)(ar0 * PAD_ + ac0) * 4;
    uint32_t aDst1 = (uint32_t)(ar1 * PAD_ + ac1) * 4;
    int br[4], bc[4];
    const float* Bsrc[4];
    uint32_t bDst[4];
    #pragma unroll
    for (int j = 0; j < 4; j++) {
        int s = tid + 512 * j;
        br[j] = s >> 3; bc[j] = (s & 7) * 4;
        Bsrc[j] = B + (size_t)(n0 + br[j]) * Ktot + bc[j];
        bDst[j] = (uint32_t)(ABUF_ + br[j] * PAD_ + bc[j]) * 4;
    }

    float acc[2][8][4];
    #pragma unroll
    for (int i = 0; i < 2; i++)
        #pragma unroll
        for (int j = 0; j < 8; j++)
            #pragma unroll
            for (int c = 0; c < 4; c++) acc[i][j][c] = 0.f;

    int KT = Ktot >> 5;

    auto copyTile = [&](int kt, int stg) {
        uint32_t so = sbase + (uint32_t)(stg * STG_W * 4);
        int ko = kt * 32;
        CP16(so + aDst0, Asrc0 + ko);
        CP16(so + aDst1, Asrc1 + ko);
        #pragma unroll
        for (int j = 0; j < 4; j++)
            CP16(so + bDst[j], Bsrc[j] + ko);
        CP_COMMIT();
    };

    copyTile(0, 0);
    copyTile(1, 1);

    int r4 = lane >> 2, c4 = lane & 3;

    for (int kt = 0; kt < KT; kt++) {
        if (kt + 1 < KT) CP_WAIT1(); else CP_WAIT0();
        __syncthreads();

        uint32_t* As = dsm + (kt % 3) * STG_W;
        uint32_t* Bs = As + ABUF_;
        #pragma unroll
        for (int ks = 0; ks < 4; ks++) {
            int kb = ks * 8;
            uint32_t a[2][4], b[8][2];
            #pragma unroll
            for (int mi = 0; mi < 2; mi++) {
                int rr = (m0w + mi * 16 + r4) * PAD_ + kb + c4;
                a[mi][0] = As[rr];
                a[mi][1] = As[rr + 8 * PAD_];
                a[mi][2] = As[rr + 4];
                a[mi][3] = As[rr + 8 * PAD_ + 4];
            }
            #pragma unroll
            for (int ni = 0; ni < 8; ni++) {
                int rr = (n0w + ni * 8 + r4) * PAD_ + kb + c4;
                b[ni][0] = Bs[rr];
                b[ni][1] = Bs[rr + 4];
            }
            #pragma unroll
            for (int mi = 0; mi < 2; mi++)
                #pragma unroll
                for (int ni = 0; ni < 8; ni++)
                    mma_tf32(acc[mi][ni], a[mi], b[ni]);
        }

        if (kt + 2 < KT) copyTile(kt + 2, (kt + 2) % 3);
    }

    #pragma unroll
    for (int mi = 0; mi < 2; mi++) {
        #pragma unroll
        for (int half_m = 0; half_m < 2; half_m++) {
            int m = m0 + m0w + mi * 16 + half_m * 8 + r4;
            int bb = m >> 11, ss = m & (S_ - 1);
            #pragma unroll
            for (int ni = 0; ni < 8; ni++) {
                int n = n0 + n0w + ni * 8 + c4 * 2;
                float2 o;
                o.x = acc[mi][ni][half_m * 2 + 0] * alpha;
                o.y = acc[mi][ni][half_m * 2 + 1] * alpha;
                if (MODE == 1) {
                    o.x = f2tf32f(o.x);
                    o.y = f2tf32f(o.y);
                    int h = n >> 7, dh = n & 127;
                    *(float2*)(C + (((size_t)bb * H_ + h) * S_ + ss) * DH_ + dh) = o;
                } else {
                    *(float2*)(C + (size_t)m * ldc + n) = o;
                }
            }
        }
    }
}

// ============================ tf32 flash attention (512 thr) ===============
// q tile 128, kv tile 64, 16 warps: warp (qg, half) with qg=wid>>1, half=wid&1.
// S:  warp tile 16q x 32kv (half picks kv cols).
// PV: warp tile 16q x 64dh (half picks dh cols).
// Row softmax state (m,l) + cross-pair partials in SMEM.
#define QP_ 132
#define VP_ 68
#define ATTN_W (128 * QP_ + 64 * QP_ + 128 * VP_ + 128 * VP_ + 768)
#define ATTN_SMEM (ATTN_W * 4)

__global__ __launch_bounds__(512) void attn_tc_kernel() {
    extern __shared__ __align__(16) uint32_t asm_[];
    uint32_t* Qs = asm_;
    uint32_t* Ks = Qs + 128 * QP_;
    uint32_t* Vt = Ks + 64 * QP_;
    uint32_t* Ps = Vt + 128 * VP_;
    float* sM  = (float*)(Ps + 128 * VP_);   // [128]
    float* sL  = sM + 128;                   // [128]
    float* sPM = sL + 128;                   // [128][2]
    float* sPS = sPM + 256;                  // [128][2]

    int bh = blockIdx.y;
    int q0 = blockIdx.x * 128;
    const float* Qg = g_q + (size_t)bh * S_ * DH_;
    const float* Kg = g_k + (size_t)bh * S_ * DH_;
    const float* Vg = g_v + (size_t)bh * S_ * DH_;

    int tid = threadIdx.x;
    int wid = tid >> 5;
    int lane = tid & 31;
    int r4 = lane >> 2, c4 = lane & 3;
    int qg = wid >> 1, half = wid & 1;
    int rowA = qg * 16 + r4, rowB = rowA + 8;

    // load Q (tf32 bits)
    for (int i = tid; i < 128 * 32; i += 512) {
        int r = i >> 5, c = (i & 31) * 4;
        *(uint4*)&Qs[r * QP_ + c] = *(const uint4*)(Qg + (size_t)(q0 + r) * DH_ + c);
    }
    if (tid < 128) { sM[tid] = -1e30f; sL[tid] = 0.f; }

    float4 kreg[4], vreg[4];
    auto loadK = [&](int j0) {
        #pragma unroll
        for (int j = 0; j < 4; j++) {
            int i = tid + 512 * j;
            int r = i >> 5, c = (i & 31) * 4;
            kreg[j] = *(const float4*)(Kg + (size_t)(j0 + r) * DH_ + c);
        }
    };
    auto loadV = [&](int j0) {
        #pragma unroll
        for (int j = 0; j < 4; j++) {
            int i = tid + 512 * j;
            int r = i & 63, c = (i >> 6) * 4;
            vreg[j] = *(const float4*)(Vg + (size_t)(j0 + r) * DH_ + c);
        }
    };

    loadK(0);
    loadV(0);

    float o[8][4];
    #pragma unroll
    for (int ni = 0; ni < 8; ni++)
        #pragma unroll
        for (int c = 0; c < 4; c++) o[ni][c] = 0.f;

    for (int j0 = 0; j0 < S_; j0 += 64) {
        __syncthreads();   // prev tile's Ks/Vt/Ps reads done; Q/state visible iter 0
        #pragma unroll
        for (int j = 0; j < 4; j++) {
            int i = tid + 512 * j;
            int r = i >> 5, c = (i & 31) * 4;
            *(uint4*)&Ks[r * QP_ + c] = *(const uint4*)&kreg[j];
        }
        #pragma unroll
        for (int j = 0; j < 4; j++) {
            int i = tid + 512 * j;
            int r = i & 63, c = (i >> 6) * 4;
            Vt[(c + 0) * VP_ + r] = __float_as_uint(vreg[j].x);
            Vt[(c + 1) * VP_ + r] = __float_as_uint(vreg[j].y);
            Vt[(c + 2) * VP_ + r] = __float_as_uint(vreg[j].z);
            Vt[(c + 3) * VP_ + r] = __float_as_uint(vreg[j].w);
        }
        __syncthreads();

        bool more = (j0 + 64) < S_;
        if (more) loadK(j0 + 64);

        // S = Q K^T  (16q x 32kv per warp)
        float sf[4][4];
        #pragma unroll
        for (int ni = 0; ni < 4; ni++)
            #pragma unroll
            for (int c = 0; c < 4; c++) sf[ni][c] = 0.f;

        #pragma unroll
        for (int ks = 0; ks < 16; ks++) {
            int kb = ks * 8;
            uint32_t a[4];
            int ar = (qg * 16 + r4) * QP_ + kb + c4;
            a[0] = Qs[ar];
            a[1] = Qs[ar + 8 * QP_];
            a[2] = Qs[ar + 4];
            a[3] = Qs[ar + 8 * QP_ + 4];
            #pragma unroll
            for (int ni = 0; ni < 4; ni++) {
                uint32_t b[2];
                int br = (half * 32 + ni * 8 + r4) * QP_ + kb + c4;
                b[0] = Ks[br];
                b[1] = Ks[br + 4];
                mma_tf32(sf[ni], a, b);
            }
        }

        if (more) loadV(j0 + 64);

        // partial row max (this warp's 32 kv cols)
        float mxA = -1e30f, mxB = -1e30f;
        #pragma unroll
        for (int ni = 0; ni < 4; ni++) {
            mxA = fmaxf(mxA, fmaxf(sf[ni][0], sf[ni][1]));
            mxB = fmaxf(mxB, fmaxf(sf[ni][2], sf[ni][3]));
        }
        mxA = fmaxf(mxA, __shfl_xor_sync(0xffffffffu, mxA, 1));
        mxA = fmaxf(mxA, __shfl_xor_sync(0xffffffffu, mxA, 2));
        mxB = fmaxf(mxB, __shfl_xor_sync(0xffffffffu, mxB, 1));
        mxB = fmaxf(mxB, __shfl_xor_sync(0xffffffffu, mxB, 2));
        if (c4 == 0) {
            sPM[rowA * 2 + half] = mxA;
            sPM[rowB * 2 + half] = mxB;
        }
        __syncthreads();

        float gmA = fmaxf(sPM[rowA * 2], sPM[rowA * 2 + 1]);
        float gmB = fmaxf(sPM[rowB * 2], sPM[rowB * 2 + 1]);
        float moldA = sM[rowA], moldB = sM[rowB];
        float mnA = fmaxf(moldA, gmA), mnB = fmaxf(moldB, gmB);
        float scA = __expf(moldA - mnA), scB = __expf(moldB - mnB);
        float sA = 0.f, sB = 0.f;
        int prA = rowA * VP_ + half * 32;
        int prB = rowB * VP_ + half * 32;
        #pragma unroll
        for (int ni = 0; ni < 4; ni++) {
            float e0 = __expf(sf[ni][0] - mnA);
            float e1 = __expf(sf[ni][1] - mnA);
            float e2 = __expf(sf[ni][2] - mnB);
            float e3 = __expf(sf[ni][3] - mnB);
            sA += e0 + e1; sB += e2 + e3;
            int cc = ni * 8 + c4 * 2;
            Ps[prA + cc] = f2tf32(e0); Ps[prA + cc + 1] = f2tf32(e1);
            Ps[prB + cc] = f2tf32(e2); Ps[prB + cc + 1] = f2tf32(e3);
        }
        sA += __shfl_xor_sync(0xffffffffu, sA, 1);
        sA += __shfl_xor_sync(0xffffffffu, sA, 2);
        sB += __shfl_xor_sync(0xffffffffu, sB, 1);
        sB += __shfl_xor_sync(0xffffffffu, sB, 2);
        if (c4 == 0) {
            sPS[rowA * 2 + half] = sA;
            sPS[rowB * 2 + half] = sB;
        }
        #pragma unroll
        for (int ni = 0; ni < 8; ni++) {
            o[ni][0] *= scA; o[ni][1] *= scA;
            o[ni][2] *= scB; o[ni][3] *= scB;
        }
        __syncthreads();   // Ps + psum visible

        if (half == 0 && c4 == 0) {
            sL[rowA] = sL[rowA] * scA + sPS[rowA * 2] + sPS[rowA * 2 + 1];
            sM[rowA] = mnA;
            sL[rowB] = sL[rowB] * scB + sPS[rowB * 2] + sPS[rowB * 2 + 1];
            sM[rowB] = mnB;
        }

        // O += P V  (16q x 64dh per warp; half picks dh range)
        #pragma unroll
        for (int ks = 0; ks < 8; ks++) {
            int kb = ks * 8;
            uint32_t a[4];
            int ar = (qg * 16 + r4) * VP_ + kb + c4;
            a[0] = Ps[ar];
            a[1] = Ps[ar + 8 * VP_];
            a[2] = Ps[ar + 4];
            a[3] = Ps[ar + 8 * VP_ + 4];
            #pragma unroll
            for (int ni = 0; ni < 8; ni++) {
                uint32_t b[2];
                int br = (half * 64 + ni * 8 + r4) * VP_ + kb + c4;
                b[0] = Vt[br];
                b[1] = Vt[br + 4];
                mma_tf32(o[ni], a, b);
            }
        }
    }

    __syncthreads();   // final sL updates visible
    float invA = 1.f / sL[rowA], invB = 1.f / sL[rowB];
    float* OgA = g_res + (size_t)bh * S_ * DH_ + (size_t)(q0 + rowA) * DH_ + half * 64;
    float* OgB = OgA + 8 * DH_;
    #pragma unroll
    for (int ni = 0; ni < 8; ni++) {
        int cc = ni * 8 + c4 * 2;
        float2 oa, ob;
        oa.x = o[ni][0] * invA; oa.y = o[ni][1] * invA;
        ob.x = o[ni][2] * invB; ob.y = o[ni][3] * invB;
        *(float2*)(OgA + cc) = oa;
        *(float2*)(OgB + cc) = ob;
    }
}

// ---------------------------------------------------------------------------
extern "C" void kernel_launch(void* const* d_in, const int* in_sizes, int n_in,
                              void* d_out, int out_size) {
    const float* q_src = (const float*)d_in[0];
    const float* k_src = (const float*)d_in[1];
    const float* v_src = (const float*)d_in[2];
    const float* Wq    = (const float*)d_in[3];
    const float* Wk    = (const float*)d_in[4];
    const float* Wv    = (const float*)d_in[5];
    const float* Wo    = (const float*)d_in[6];
    const float* sel_v = (const float*)d_in[7];
    const float* sel_o = (const float*)d_in[8];
    float* outp = (float*)d_out;

    cudaFuncSetAttribute(attn_tc_kernel, cudaFuncAttributeMaxDynamicSharedMemorySize, ATTN_SMEM);
    cudaFuncSetAttribute(gemm_tf32<0>, cudaFuncAttributeMaxDynamicSharedMemorySize, GSMEM_BYTES);
    cudaFuncSetAttribute(gemm_tf32<1>, cudaFuncAttributeMaxDynamicSharedMemorySize, GSMEM_BYTES);

    float *gq, *gk, *gyall, *gaexp, *gwvT, *gwoT;
    float *gqc, *gkc, *gvc, *gwqc, *gwkc;
    cudaGetSymbolAddress((void**)&gq, g_q);
    cudaGetSymbolAddress((void**)&gk, g_k);
    cudaGetSymbolAddress((void**)&gyall, g_yall);
    cudaGetSymbolAddress((void**)&gaexp, g_aexp);
    cudaGetSymbolAddress((void**)&gwvT, g_wvT);
    cudaGetSymbolAddress((void**)&gwoT, g_woT);
    cudaGetSymbolAddress((void**)&gqc, g_qc);
    cudaGetSymbolAddress((void**)&gkc, g_kc);
    cudaGetSymbolAddress((void**)&gvc, g_vc);
    cudaGetSymbolAddress((void**)&gwqc, g_wqc);
    cudaGetSymbolAddress((void**)&gwkc, g_wkc);

    const float scale = 0.29730177875068026f;  // 128^-0.25

    router_kernel<<<TOK_, 256>>>(q_src, k_src, sel_v, sel_o);

    int n4a = TOK_ * D_ / 4, n4w = D_ * D_ / 4;
    conv_kernel<<<(n4a + 255) / 256, 256>>>(q_src, gqc, n4a);
    conv_kernel<<<(n4a + 255) / 256, 256>>>(k_src, gkc, n4a);
    conv_kernel<<<(n4a + 255) / 256, 256>>>(v_src, gvc, n4a);
    conv_kernel<<<(n4w + 255) / 256, 256>>>(Wq, gwqc, n4w);
    conv_kernel<<<(n4w + 255) / 256, 256>>>(Wk, gwkc, n4w);

    transpose_kernel<<<dim3(DH_ / 32, D_ / 32, GE_), dim3(32, 8)>>>(Wv, gwvT, D_, DH_);
    transpose_kernel<<<dim3(D_ / 32, KEXP_ / 32, 1), dim3(32, 8)>>>(Wo, gwoT, KEXP_, D_);

    // merged q/k projections: M=4096, N=1024, K=1024; z=0 -> q, z=1 -> k
    gemm_tf32<1><<<dim3(D_ / 256, TOK_ / 128, 2), 512, GSMEM_BYTES>>>(
        gqc, gwqc, gq, D_, 0, scale, gkc, gwkc, gk);

    // all-expert V: M=4096, N=4096, K=1024
    gemm_tf32<0><<<dim3(KEXP_ / 256, TOK_ / 128), 512, GSMEM_BYTES>>>(
        gvc, gwvT, gyall, D_, KEXP_, 1.0f, nullptr, nullptr, nullptr);
    vgate_kernel<<<TOK_ * H_ * 32 / 256, 256>>>();

    attn_tc_kernel<<<dim3(S_ / 128, B_ * H_), 512, ATTN_SMEM>>>();

    expand_kernel<<<TOK_ * GE_ * 32 / 256, 256>>>();
    // out: M=4096, N=1024, K=4096
    gemm_tf32<0><<<dim3(D_ / 256, TOK_ / 128), 512, GSMEM_BYTES>>>(
        gaexp, gwoT, outp, KEXP_, D_, 1.0f, nullptr, nullptr, nullptr);
}

// round 10
// speedup vs baseline: 1.6775x; 1.6775x over previous
#include <cuda_runtime.h>
#include <cuda_fp16.h>
#include <math.h>
#include <stdint.h>

// ---------------------------------------------------------------------------
// SwitchHeadCore: B=2,S=2048,D=1024,H=8,E=4,K=2,DH=128
// fp16 m16n8k16 mma everywhere (fp32 accumulate): pre-converted fp16 operands,
// 512-thread cp.async GEMMs (BK=64), 256-thread fp16 flash attention.
// ---------------------------------------------------------------------------

#define B_ 2
#define S_ 2048
#define D_ 1024
#define H_ 8
#define E_ 4
#define DH_ 128
#define TOK_ (B_ * S_)              // 4096
#define GE_ (H_ * E_)               // 32
#define KEXP_ 4096                  // H*E*DH

__device__ __align__(16) __half g_q[TOK_ * D_];     // [B,H,S,DH]
__device__ __align__(16) __half g_k[TOK_ * D_];
__device__ __align__(16) __half g_v[TOK_ * D_];
__device__ __align__(16) float  g_res[TOK_ * D_];   // fp32
__device__ float g_gv[TOK_ * GE_];
__device__ float g_go[TOK_ * GE_];
__device__ __align__(16) float  g_yall[(size_t)TOK_ * KEXP_]; // fp32
__device__ __align__(16) __half g_aexp[(size_t)TOK_ * KEXP_];
__device__ __align__(16) __half g_wvT[(size_t)KEXP_ * D_];    // [(h,e,dh), d]
__device__ __align__(16) __half g_woT[(size_t)D_ * KEXP_];    // [o, (h,e,dh)]
__device__ __align__(16) __half g_qc[TOK_ * D_];
__device__ __align__(16) __half g_kc[TOK_ * D_];
__device__ __align__(16) __half g_vc[TOK_ * D_];
__device__ __align__(16) __half g_wqc[D_ * D_];
__device__ __align__(16) __half g_wkc[D_ * D_];

// ============================ helpers ======================================
__device__ __forceinline__ void mma_f16(float* d, const uint32_t* a, const uint32_t* b) {
    asm volatile(
        "mma.sync.aligned.m16n8k16.row.col.f32.f16.f16.f32 "
        "{%0,%1,%2,%3}, {%4,%5,%6,%7}, {%8,%9}, {%0,%1,%2,%3};\n"
        : "+f"(d[0]), "+f"(d[1]), "+f"(d[2]), "+f"(d[3])
        : "r"(a[0]), "r"(a[1]), "r"(a[2]), "r"(a[3]), "r"(b[0]), "r"(b[1]));
}
__device__ __forceinline__ uint32_t smem_u32(const void* p) {
    uint32_t a;
    asm("{ .reg .u64 t; cvta.to.shared.u64 t, %1; cvt.u32.u64 %0, t; }" : "=r"(a) : "l"(p));
    return a;
}
__device__ __forceinline__ uint32_t pack_h2(float x, float y) {
    __half2 h = __floats2half2_rn(x, y);
    return *(uint32_t*)&h;
}
#define CP16(dst, src) \
    asm volatile("cp.async.cg.shared.global [%0], [%1], 16;" :: "r"(dst), "l"(src))
#define CP_COMMIT() asm volatile("cp.async.commit_group;")
#define CP_WAIT1() asm volatile("cp.async.wait_group 1;")
#define CP_WAIT0() asm volatile("cp.async.wait_group 0;")

// ============================ router =======================================
__global__ void router_kernel(const float* __restrict__ q_src,
                              const float* __restrict__ k_src,
                              const float* __restrict__ sel_v,
                              const float* __restrict__ sel_o) {
    int t = blockIdx.x;
    int tid = threadIdx.x;
    __shared__ float xs[D_];
    __shared__ float sg[GE_];

    for (int r = 0; r < 2; r++) {
        const float* src = (r == 0) ? k_src : q_src;
        const float* sel = (r == 0) ? sel_v : sel_o;
        float* gout      = (r == 0) ? g_gv  : g_go;

        for (int i = tid; i < D_ / 4; i += blockDim.x)
            ((float4*)xs)[i] = ((const float4*)(src + (size_t)t * D_))[i];
        __syncthreads();

        int g = tid >> 3;
        int l8 = tid & 7;
        const float* w = sel + (size_t)g * D_;
        float sum = 0.f;
        for (int d = l8; d < D_; d += 8) sum += xs[d] * w[d];
        sum += __shfl_xor_sync(0xffffffffu, sum, 1);
        sum += __shfl_xor_sync(0xffffffffu, sum, 2);
        sum += __shfl_xor_sync(0xffffffffu, sum, 4);
        if (l8 == 0) sg[g] = 1.f / (1.f + __expf(-sum));
        __syncthreads();

        if (tid < H_) {
            int h = tid;
            float vals[4];
            #pragma unroll
            for (int e = 0; e < 4; e++) vals[e] = sg[h * 4 + e];
            int i1 = 0;
            #pragma unroll
            for (int e = 1; e < 4; e++) if (vals[e] > vals[i1]) i1 = e;
            int i2 = -1;
            #pragma unroll
            for (int e = 0; e < 4; e++) {
                if (e == i1) continue;
                if (i2 < 0 || vals[e] > vals[i2]) i2 = e;
            }
            #pragma unroll
            for (int e = 0; e < 4; e++)
                gout[(size_t)t * GE_ + h * 4 + e] = (e == i1 || e == i2) ? vals[e] : 0.f;
        }
        __syncthreads();
    }
}

// ============================ convert (fp32 -> fp16) =======================
__global__ void conv_kernel(const float* __restrict__ src, __half* __restrict__ dst, int n4) {
    int i = blockIdx.x * blockDim.x + threadIdx.x;
    if (i >= n4) return;
    float4 v = ((const float4*)src)[i];
    __half2 h0 = __floats2half2_rn(v.x, v.y);
    __half2 h1 = __floats2half2_rn(v.z, v.w);
    ((__half2*)dst)[i * 2 + 0] = h0;
    ((__half2*)dst)[i * 2 + 1] = h1;
}

// ============================ transpose (emit fp16) ========================
__global__ void transpose_kernel(const float* __restrict__ src, __half* __restrict__ dst,
                                 int R, int C) {
    __shared__ float tile[32][33];
    size_t zo = (size_t)blockIdx.z * R * C;
    src += zo; dst += zo;
    int r0 = blockIdx.y * 32, c0 = blockIdx.x * 32;
    int x = threadIdx.x, y = threadIdx.y;
    #pragma unroll
    for (int i = 0; i < 32; i += 8)
        tile[y + i][x] = src[(size_t)(r0 + y + i) * C + c0 + x];
    __syncthreads();
    #pragma unroll
    for (int i = 0; i < 32; i += 8)
        dst[(size_t)(c0 + y + i) * R + r0 + x] = __float2half_rn(tile[x][y + i]);
}

// ============================ gated expand (O), fp16 out ===================
__global__ __launch_bounds__(256) void expand_kernel() {
    int idx = blockIdx.x * 256 + threadIdx.x;   // 4096*32*32
    int dh4 = idx & 31;
    int he = (idx >> 5) & 31;
    int t = idx >> 10;
    int h = he >> 2;
    int b = t >> 11, s = t & (S_ - 1);
    float g = g_go[(size_t)t * GE_ + he];
    float4 r = *(const float4*)&g_res[(((size_t)b * H_ + h) * S_ + s) * DH_ + dh4 * 4];
    __half2 h0 = __floats2half2_rn(r.x * g, r.y * g);
    __half2 h1 = __floats2half2_rn(r.z * g, r.w * g);
    __half2* dst = (__half2*)&g_aexp[(size_t)t * KEXP_ + he * 128 + dh4 * 4];
    dst[0] = h0; dst[1] = h1;
}

// ============================ gated reduce (V), fp16 out ===================
__global__ __launch_bounds__(256) void vgate_kernel() {
    int idx = blockIdx.x * 256 + threadIdx.x;   // 4096*8*32
    int dh4 = idx & 31;
    int h = (idx >> 5) & 7;
    int t = idx >> 8;
    int b = t >> 11, s = t & (S_ - 1);
    const float* y = g_yall + (size_t)t * KEXP_ + h * 512 + dh4 * 4;
    const float* g = g_gv + (size_t)t * GE_ + h * 4;
    float4 acc = make_float4(0.f, 0.f, 0.f, 0.f);
    #pragma unroll
    for (int e = 0; e < 4; e++) {
        float ge = g[e];
        float4 ye = *(const float4*)(y + e * 128);
        acc.x += ge * ye.x; acc.y += ge * ye.y; acc.z += ge * ye.z; acc.w += ge * ye.w;
    }
    __half2 h0 = __floats2half2_rn(acc.x, acc.y);
    __half2 h1 = __floats2half2_rn(acc.z, acc.w);
    __half2* dst = (__half2*)&g_v[(((size_t)b * H_ + h) * S_ + s) * DH_ + dh4 * 4];
    dst[0] = h0; dst[1] = h1;
}

// ============================ fp16 mma GEMM (cp.async, 512 thr) ============
// C[M,N] = alpha * A[M,K] @ B[N,K]^T, A/B fp16.  Block 128x256xBK64,
// 16 warps (4m x 4n), warp tile 32x64.  3-stage cp.async.
// SMEM rows = 32 words (64 halves) padded to 36.
// MODE 0: row-major fp32 C.  MODE 1: qk merged (z picks), C [B,H,S,DH] fp16.
#define PADH_ 36
#define ABUF_ (128 * PADH_)
#define BBUF_ (256 * PADH_)
#define STG_W (ABUF_ + BBUF_)           // 13824 words
#define GSMEM_BYTES (3 * STG_W * 4)     // 165888

template<int MODE>
__global__ __launch_bounds__(512) void gemm_f16(const __half* __restrict__ A,
                                                const __half* __restrict__ B,
                                                void* __restrict__ Cv,
                                                int Ktot, int ldc, float alpha,
                                                const __half* __restrict__ A2,
                                                const __half* __restrict__ B2,
                                                void* __restrict__ C2v) {
    extern __shared__ __align__(16) uint32_t dsm[];
    uint32_t sbase = smem_u32(dsm);

    int tid = threadIdx.x;
    int wid = tid >> 5;
    int lane = tid & 31;
    int m0 = blockIdx.y * 128, n0 = blockIdx.x * 256;
    int m0w = (wid >> 2) * 32, n0w = (wid & 3) * 64;

    void* Cp = Cv;
    if (MODE == 1 && blockIdx.z == 1) { A = A2; B = B2; Cp = C2v; }

    // A tile: 128 rows x 64 halves = 1024 16B chunks; 2 per thread.
    int ar0 = tid >> 3, ao0 = (tid & 7) * 8;             // halves offset
    int aS1 = tid + 512;
    int ar1 = aS1 >> 3, ao1 = (aS1 & 7) * 8;
    const __half* Asrc0 = A + (size_t)(m0 + ar0) * Ktot + ao0;
    const __half* Asrc1 = A + (size_t)(m0 + ar1) * Ktot + ao1;
    uint32_t aDst0 = (uint32_t)(ar0 * PADH_ + (ao0 >> 1)) * 4;
    uint32_t aDst1 = (uint32_t)(ar1 * PADH_ + (ao1 >> 1)) * 4;
    // B tile: 256 rows x 64 halves = 2048 chunks; 4 per thread.
    const __half* Bsrc[4];
    uint32_t bDst[4];
    #pragma unroll
    for (int j = 0; j < 4; j++) {
        int s = tid + 512 * j;
        int brr = s >> 3, bo = (s & 7) * 8;
        Bsrc[j] = B + (size_t)(n0 + brr) * Ktot + bo;
        bDst[j] = (uint32_t)(ABUF_ + brr * PADH_ + (bo >> 1)) * 4;
    }

    float acc[2][8][4];
    #pragma unroll
    for (int i = 0; i < 2; i++)
        #pragma unroll
        for (int j = 0; j < 8; j++)
            #pragma unroll
            for (int c = 0; c < 4; c++) acc[i][j][c] = 0.f;

    int KT = Ktot >> 6;   // BK=64

    auto copyTile = [&](int kt, int stg) {
        uint32_t so = sbase + (uint32_t)(stg * STG_W * 4);
        int ko = kt * 64;
        CP16(so + aDst0, Asrc0 + ko);
        CP16(so + aDst1, Asrc1 + ko);
        #pragma unroll
        for (int j = 0; j < 4; j++)
            CP16(so + bDst[j], Bsrc[j] + ko);
        CP_COMMIT();
    };

    copyTile(0, 0);
    copyTile(1, 1);

    int r4 = lane >> 2, c4 = lane & 3;

    for (int kt = 0; kt < KT; kt++) {
        if (kt + 1 < KT) CP_WAIT1(); else CP_WAIT0();
        __syncthreads();

        uint32_t* As = dsm + (kt % 3) * STG_W;
        uint32_t* Bs = As + ABUF_;
        #pragma unroll
        for (int ks = 0; ks < 4; ks++) {
            int kb = ks * 8;
            uint32_t a[2][4], b[8][2];
            #pragma unroll
            for (int mi = 0; mi < 2; mi++) {
                int rr = (m0w + mi * 16 + r4) * PADH_ + kb + c4;
                a[mi][0] = As[rr];
                a[mi][1] = As[rr + 8 * PADH_];
                a[mi][2] = As[rr + 4];
                a[mi][3] = As[rr + 8 * PADH_ + 4];
            }
            #pragma unroll
            for (int ni = 0; ni < 8; ni++) {
                int rr = (n0w + ni * 8 + r4) * PADH_ + kb + c4;
                b[ni][0] = Bs[rr];
                b[ni][1] = Bs[rr + 4];
            }
            #pragma unroll
            for (int mi = 0; mi < 2; mi++)
                #pragma unroll
                for (int ni = 0; ni < 8; ni++)
                    mma_f16(acc[mi][ni], a[mi], b[ni]);
        }

        if (kt + 2 < KT) copyTile(kt + 2, (kt + 2) % 3);
    }

    #pragma unroll
    for (int mi = 0; mi < 2; mi++) {
        #pragma unroll
        for (int half_m = 0; half_m < 2; half_m++) {
            int m = m0 + m0w + mi * 16 + half_m * 8 + r4;
            int bb = m >> 11, ss = m & (S_ - 1);
            #pragma unroll
            for (int ni = 0; ni < 8; ni++) {
                int n = n0 + n0w + ni * 8 + c4 * 2;
                float ox = acc[mi][ni][half_m * 2 + 0] * alpha;
                float oy = acc[mi][ni][half_m * 2 + 1] * alpha;
                if (MODE == 1) {
                    int h = n >> 7, dh = n & 127;
                    __half2 hv = __floats2half2_rn(ox, oy);
                    *(__half2*)((__half*)Cp + (((size_t)bb * H_ + h) * S_ + ss) * DH_ + dh) = hv;
                } else {
                    float2 o2 = make_float2(ox, oy);
                    *(float2*)((float*)Cp + (size_t)m * ldc + n) = o2;
                }
            }
        }
    }
}

// ============================ fp16 flash attention (256 thr) ===============
// q tile 128 (8 warps x 16 rows), kv tile 64.  All SMEM tiles fp16 (word = h2).
// Qs[128][68w], Ks[64][68w], Vt[128][36w] (dh-major), Ps[128][36w].
#define QPH_ 68
#define VPH_ 36
#define ATTN_W (128 * QPH_ + 64 * QPH_ + 128 * VPH_ + 128 * VPH_)
#define ATTN_SMEM (ATTN_W * 4)          // 89088

__global__ __launch_bounds__(256) void attn_tc_kernel() {
    extern __shared__ __align__(16) uint32_t asm_[];
    uint32_t* Qs = asm_;
    uint32_t* Ks = Qs + 128 * QPH_;
    uint32_t* Vt = Ks + 64 * QPH_;
    uint32_t* Ps = Vt + 128 * VPH_;
    __half* Vth = (__half*)Vt;

    int bh = blockIdx.y;
    int q0 = blockIdx.x * 128;
    const __half* Qg = g_q + (size_t)bh * S_ * DH_;
    const __half* Kg = g_k + (size_t)bh * S_ * DH_;
    const __half* Vg = g_v + (size_t)bh * S_ * DH_;

    int tid = threadIdx.x;
    int wid = tid >> 5;
    int lane = tid & 31;
    int r4 = lane >> 2, c4 = lane & 3;
    int m0w = wid * 16;

    // load Q: 128 rows x 128 halves = 2048 16B chunks
    for (int i = tid; i < 2048; i += 256) {
        int r = i >> 4, wo = (i & 15) * 4;
        *(uint4*)&Qs[r * QPH_ + wo] = *(const uint4*)(Qg + (size_t)(q0 + r) * DH_ + (i & 15) * 8);
    }

    uint4 kreg[4], vreg[4];
    auto loadK = [&](int j0) {
        #pragma unroll
        for (int j = 0; j < 4; j++) {
            int i = tid + 256 * j;
            int r = i >> 4, ho = (i & 15) * 8;
            kreg[j] = *(const uint4*)(Kg + (size_t)(j0 + r) * DH_ + ho);
        }
    };
    auto loadV = [&](int j0) {
        #pragma unroll
        for (int j = 0; j < 4; j++) {
            int i = tid + 256 * j;
            int r = i & 63, c8 = (i >> 6) * 8;
            vreg[j] = *(const uint4*)(Vg + (size_t)(j0 + r) * DH_ + c8);
        }
    };

    loadK(0);
    loadV(0);

    float o[16][4];
    #pragma unroll
    for (int ni = 0; ni < 16; ni++)
        #pragma unroll
        for (int c = 0; c < 4; c++) o[ni][c] = 0.f;
    float mA = -1e30f, mB = -1e30f, lA = 0.f, lB = 0.f;

    for (int j0 = 0; j0 < S_; j0 += 64) {
        __syncthreads();
        #pragma unroll
        for (int j = 0; j < 4; j++) {
            int i = tid + 256 * j;
            int r = i >> 4, wo = (i & 15) * 4;
            *(uint4*)&Ks[r * QPH_ + wo] = kreg[j];
        }
        #pragma unroll
        for (int j = 0; j < 4; j++) {
            int i = tid + 256 * j;
            int r = i & 63, c8 = (i >> 6) * 8;
            const __half* vh = (const __half*)&vreg[j];
            #pragma unroll
            for (int jj = 0; jj < 8; jj++)
                Vth[(c8 + jj) * (VPH_ * 2) + r] = vh[jj];
        }
        __syncthreads();

        bool more = (j0 + 64) < S_;
        if (more) loadK(j0 + 64);

        // S = Q K^T  (16q x 64kv per warp), K dim = 128 halves -> 8 steps
        float sf[8][4];
        #pragma unroll
        for (int ni = 0; ni < 8; ni++)
            #pragma unroll
            for (int c = 0; c < 4; c++) sf[ni][c] = 0.f;

        #pragma unroll
        for (int ks = 0; ks < 8; ks++) {
            int kb = ks * 8;
            uint32_t a[4];
            int ar = (m0w + r4) * QPH_ + kb + c4;
            a[0] = Qs[ar];
            a[1] = Qs[ar + 8 * QPH_];
            a[2] = Qs[ar + 4];
            a[3] = Qs[ar + 8 * QPH_ + 4];
            #pragma unroll
            for (int ni = 0; ni < 8; ni++) {
                uint32_t b[2];
                int br = (ni * 8 + r4) * QPH_ + kb + c4;
                b[0] = Ks[br];
                b[1] = Ks[br + 4];
                mma_f16(sf[ni], a, b);
            }
        }

        if (more) loadV(j0 + 64);

        float mxA = -1e30f, mxB = -1e30f;
        #pragma unroll
        for (int ni = 0; ni < 8; ni++) {
            mxA = fmaxf(mxA, fmaxf(sf[ni][0], sf[ni][1]));
            mxB = fmaxf(mxB, fmaxf(sf[ni][2], sf[ni][3]));
        }
        mxA = fmaxf(mxA, __shfl_xor_sync(0xffffffffu, mxA, 1));
        mxA = fmaxf(mxA, __shfl_xor_sync(0xffffffffu, mxA, 2));
        mxB = fmaxf(mxB, __shfl_xor_sync(0xffffffffu, mxB, 1));
        mxB = fmaxf(mxB, __shfl_xor_sync(0xffffffffu, mxB, 2));
        float mnA = fmaxf(mA, mxA), mnB = fmaxf(mB, mxB);
        float scA = __expf(mA - mnA), scB = __expf(mB - mnB);
        float sA = 0.f, sB = 0.f;
        int prA = (m0w + r4) * VPH_;
        int prB = prA + 8 * VPH_;
        #pragma unroll
        for (int ni = 0; ni < 8; ni++) {
            float e0 = __expf(sf[ni][0] - mnA);
            float e1 = __expf(sf[ni][1] - mnA);
            float e2 = __expf(sf[ni][2] - mnB);
            float e3 = __expf(sf[ni][3] - mnB);
            sA += e0 + e1; sB += e2 + e3;
            int cw = ni * 4 + c4;
            Ps[prA + cw] = pack_h2(e0, e1);
            Ps[prB + cw] = pack_h2(e2, e3);
        }
        sA += __shfl_xor_sync(0xffffffffu, sA, 1);
        sA += __shfl_xor_sync(0xffffffffu, sA, 2);
        sB += __shfl_xor_sync(0xffffffffu, sB, 1);
        sB += __shfl_xor_sync(0xffffffffu, sB, 2);
        lA = lA * scA + sA; lB = lB * scB + sB;
        mA = mnA; mB = mnB;
        #pragma unroll
        for (int ni = 0; ni < 16; ni++) {
            o[ni][0] *= scA; o[ni][1] *= scA;
            o[ni][2] *= scB; o[ni][3] *= scB;
        }
        __syncwarp();   // Ps rows warp-private

        // O += P V  (K = 64 kv halves -> 4 steps; 128 dh cols)
        #pragma unroll
        for (int ks = 0; ks < 4; ks++) {
            int kb = ks * 8;
            uint32_t a[4];
            int ar = (m0w + r4) * VPH_ + kb + c4;
            a[0] = Ps[ar];
            a[1] = Ps[ar + 8 * VPH_];
            a[2] = Ps[ar + 4];
            a[3] = Ps[ar + 8 * VPH_ + 4];
            #pragma unroll
            for (int ni = 0; ni < 16; ni++) {
                uint32_t b[2];
                int br = (ni * 8 + r4) * VPH_ + kb + c4;
                b[0] = Vt[br];
                b[1] = Vt[br + 4];
                mma_f16(o[ni], a, b);
            }
        }
    }

    float invA = 1.f / lA, invB = 1.f / lB;
    int rA = q0 + m0w + r4;
    float* OgA = g_res + (size_t)bh * S_ * DH_ + (size_t)rA * DH_;
    float* OgB = OgA + 8 * DH_;
    #pragma unroll
    for (int ni = 0; ni < 16; ni++) {
        int cc = ni * 8 + c4 * 2;
        float2 oa, ob;
        oa.x = o[ni][0] * invA; oa.y = o[ni][1] * invA;
        ob.x = o[ni][2] * invB; ob.y = o[ni][3] * invB;
        *(float2*)(OgA + cc) = oa;
        *(float2*)(OgB + cc) = ob;
    }
}

// ---------------------------------------------------------------------------
extern "C" void kernel_launch(void* const* d_in, const int* in_sizes, int n_in,
                              void* d_out, int out_size) {
    const float* q_src = (const float*)d_in[0];
    const float* k_src = (const float*)d_in[1];
    const float* v_src = (const float*)d_in[2];
    const float* Wq    = (const float*)d_in[3];
    const float* Wk    = (const float*)d_in[4];
    const float* Wv    = (const float*)d_in[5];
    const float* Wo    = (const float*)d_in[6];
    const float* sel_v = (const float*)d_in[7];
    const float* sel_o = (const float*)d_in[8];
    float* outp = (float*)d_out;

    cudaFuncSetAttribute(attn_tc_kernel, cudaFuncAttributeMaxDynamicSharedMemorySize, ATTN_SMEM);
    cudaFuncSetAttribute(gemm_f16<0>, cudaFuncAttributeMaxDynamicSharedMemorySize, GSMEM_BYTES);
    cudaFuncSetAttribute(gemm_f16<1>, cudaFuncAttributeMaxDynamicSharedMemorySize, GSMEM_BYTES);

    __half *gq, *gk, *gaexp, *gwvT, *gwoT, *gqc, *gkc, *gvc, *gwqc, *gwkc;
    float *gyall;
    cudaGetSymbolAddress((void**)&gq, g_q);
    cudaGetSymbolAddress((void**)&gk, g_k);
    cudaGetSymbolAddress((void**)&gyall, g_yall);
    cudaGetSymbolAddress((void**)&gaexp, g_aexp);
    cudaGetSymbolAddress((void**)&gwvT, g_wvT);
    cudaGetSymbolAddress((void**)&gwoT, g_woT);
    cudaGetSymbolAddress((void**)&gqc, g_qc);
    cudaGetSymbolAddress((void**)&gkc, g_kc);
    cudaGetSymbolAddress((void**)&gvc, g_vc);
    cudaGetSymbolAddress((void**)&gwqc, g_wqc);
    cudaGetSymbolAddress((void**)&gwkc, g_wkc);

    const float scale = 0.29730177875068026f;  // 128^-0.25

    router_kernel<<<TOK_, 256>>>(q_src, k_src, sel_v, sel_o);

    int n4a = TOK_ * D_ / 4, n4w = D_ * D_ / 4;
    conv_kernel<<<(n4a + 255) / 256, 256>>>(q_src, gqc, n4a);
    conv_kernel<<<(n4a + 255) / 256, 256>>>(k_src, gkc, n4a);
    conv_kernel<<<(n4a + 255) / 256, 256>>>(v_src, gvc, n4a);
    conv_kernel<<<(n4w + 255) / 256, 256>>>(Wq, gwqc, n4w);
    conv_kernel<<<(n4w + 255) / 256, 256>>>(Wk, gwkc, n4w);

    transpose_kernel<<<dim3(DH_ / 32, D_ / 32, GE_), dim3(32, 8)>>>(Wv, gwvT, D_, DH_);
    transpose_kernel<<<dim3(D_ / 32, KEXP_ / 32, 1), dim3(32, 8)>>>(Wo, gwoT, KEXP_, D_);

    // merged q/k projections: M=4096, N=1024, K=1024; z=0 -> q, z=1 -> k
    gemm_f16<1><<<dim3(D_ / 256, TOK_ / 128, 2), 512, GSMEM_BYTES>>>(
        gqc, gwqc, gq, D_, 0, scale, gkc, gwkc, gk);

    // all-expert V: M=4096, N=4096, K=1024
    gemm_f16<0><<<dim3(KEXP_ / 256, TOK_ / 128), 512, GSMEM_BYTES>>>(
        gvc, gwvT, gyall, D_, KEXP_, 1.0f, nullptr, nullptr, nullptr);
    vgate_kernel<<<TOK_ * H_ * 32 / 256, 256>>>();

    attn_tc_kernel<<<dim3(S_ / 128, B_ * H_), 256, ATTN_SMEM>>>();

    expand_kernel<<<TOK_ * GE_ * 32 / 256, 256>>>();
    // out: M=4096, N=1024, K=4096
    gemm_f16<0><<<dim3(D_ / 256, TOK_ / 128), 512, GSMEM_BYTES>>>(
        gaexp, gwoT, outp, KEXP_, D_, 1.0f, nullptr, nullptr, nullptr);
}

// round 11
// speedup vs baseline: 1.7843x; 1.0637x over previous
#include <cuda_runtime.h>
#include <cuda_fp16.h>
#include <math.h>
#include <stdint.h>

// ---------------------------------------------------------------------------
// SwitchHeadCore: B=2,S=2048,D=1024,H=8,E=4,K=2,DH=128
// fp16 m16n8k16 everywhere (fp32 accum). cp.async GEMMs (512 thr, BK=64).
// Attention: kv-tile 128, cp.async double-buffered K/V (V pre-transposed).
// ---------------------------------------------------------------------------

#define B_ 2
#define S_ 2048
#define D_ 1024
#define H_ 8
#define E_ 4
#define DH_ 128
#define TOK_ (B_ * S_)              // 4096
#define GE_ (H_ * E_)               // 32
#define KEXP_ 4096                  // H*E*DH

__device__ __align__(16) __half g_q[TOK_ * D_];     // [B,H,S,DH]
__device__ __align__(16) __half g_k[TOK_ * D_];
__device__ __align__(16) __half g_v[TOK_ * D_];     // [B,H,S,DH]
__device__ __align__(16) __half g_vT[TOK_ * D_];    // [B,H,DH,S]
__device__ __align__(16) float  g_res[TOK_ * D_];   // fp32
__device__ float g_gv[TOK_ * GE_];
__device__ float g_go[TOK_ * GE_];
__device__ __align__(16) __half g_yall[(size_t)TOK_ * KEXP_];
__device__ __align__(16) __half g_aexp[(size_t)TOK_ * KEXP_];
__device__ __align__(16) __half g_wvT[(size_t)KEXP_ * D_];    // [(h,e,dh), d]
__device__ __align__(16) __half g_woT[(size_t)D_ * KEXP_];    // [o, (h,e,dh)]
__device__ __align__(16) __half g_qc[TOK_ * D_];
__device__ __align__(16) __half g_kc[TOK_ * D_];
__device__ __align__(16) __half g_vc[TOK_ * D_];
__device__ __align__(16) __half g_wqc[D_ * D_];
__device__ __align__(16) __half g_wkc[D_ * D_];

// ============================ helpers ======================================
__device__ __forceinline__ void mma_f16(float* d, const uint32_t* a, const uint32_t* b) {
    asm volatile(
        "mma.sync.aligned.m16n8k16.row.col.f32.f16.f16.f32 "
        "{%0,%1,%2,%3}, {%4,%5,%6,%7}, {%8,%9}, {%0,%1,%2,%3};\n"
        : "+f"(d[0]), "+f"(d[1]), "+f"(d[2]), "+f"(d[3])
        : "r"(a[0]), "r"(a[1]), "r"(a[2]), "r"(a[3]), "r"(b[0]), "r"(b[1]));
}
__device__ __forceinline__ uint32_t smem_u32(const void* p) {
    uint32_t a;
    asm("{ .reg .u64 t; cvta.to.shared.u64 t, %1; cvt.u32.u64 %0, t; }" : "=r"(a) : "l"(p));
    return a;
}
__device__ __forceinline__ uint32_t pack_h2(float x, float y) {
    __half2 h = __floats2half2_rn(x, y);
    return *(uint32_t*)&h;
}
#define CP16(dst, src) \
    asm volatile("cp.async.cg.shared.global [%0], [%1], 16;" :: "r"(dst), "l"(src))
#define CP_COMMIT() asm volatile("cp.async.commit_group;")
#define CP_WAIT1() asm volatile("cp.async.wait_group 1;")
#define CP_WAIT0() asm volatile("cp.async.wait_group 0;")

// ============================ router =======================================
__global__ void router_kernel(const float* __restrict__ q_src,
                              const float* __restrict__ k_src,
                              const float* __restrict__ sel_v,
                              const float* __restrict__ sel_o) {
    int t = blockIdx.x;
    int tid = threadIdx.x;
    __shared__ float xs[D_];
    __shared__ float sg[GE_];

    for (int r = 0; r < 2; r++) {
        const float* src = (r == 0) ? k_src : q_src;
        const float* sel = (r == 0) ? sel_v : sel_o;
        float* gout      = (r == 0) ? g_gv  : g_go;

        for (int i = tid; i < D_ / 4; i += blockDim.x)
            ((float4*)xs)[i] = ((const float4*)(src + (size_t)t * D_))[i];
        __syncthreads();

        int g = tid >> 3;
        int l8 = tid & 7;
        const float* w = sel + (size_t)g * D_;
        float sum = 0.f;
        for (int d = l8; d < D_; d += 8) sum += xs[d] * w[d];
        sum += __shfl_xor_sync(0xffffffffu, sum, 1);
        sum += __shfl_xor_sync(0xffffffffu, sum, 2);
        sum += __shfl_xor_sync(0xffffffffu, sum, 4);
        if (l8 == 0) sg[g] = 1.f / (1.f + __expf(-sum));
        __syncthreads();

        if (tid < H_) {
            int h = tid;
            float vals[4];
            #pragma unroll
            for (int e = 0; e < 4; e++) vals[e] = sg[h * 4 + e];
            int i1 = 0;
            #pragma unroll
            for (int e = 1; e < 4; e++) if (vals[e] > vals[i1]) i1 = e;
            int i2 = -1;
            #pragma unroll
            for (int e = 0; e < 4; e++) {
                if (e == i1) continue;
                if (i2 < 0 || vals[e] > vals[i2]) i2 = e;
            }
            #pragma unroll
            for (int e = 0; e < 4; e++)
                gout[(size_t)t * GE_ + h * 4 + e] = (e == i1 || e == i2) ? vals[e] : 0.f;
        }
        __syncthreads();
    }
}

// ============================ convert (fp32 -> fp16) =======================
__global__ void conv_kernel(const float* __restrict__ src, __half* __restrict__ dst, int n4) {
    int i = blockIdx.x * blockDim.x + threadIdx.x;
    if (i >= n4) return;
    float4 v = ((const float4*)src)[i];
    __half2 h0 = __floats2half2_rn(v.x, v.y);
    __half2 h1 = __floats2half2_rn(v.z, v.w);
    ((__half2*)dst)[i * 2 + 0] = h0;
    ((__half2*)dst)[i * 2 + 1] = h1;
}

// ============================ transpose (fp32 src -> fp16 dst) =============
__global__ void transpose_kernel(const float* __restrict__ src, __half* __restrict__ dst,
                                 int R, int C) {
    __shared__ float tile[32][33];
    size_t zo = (size_t)blockIdx.z * R * C;
    src += zo; dst += zo;
    int r0 = blockIdx.y * 32, c0 = blockIdx.x * 32;
    int x = threadIdx.x, y = threadIdx.y;
    #pragma unroll
    for (int i = 0; i < 32; i += 8)
        tile[y + i][x] = src[(size_t)(r0 + y + i) * C + c0 + x];
    __syncthreads();
    #pragma unroll
    for (int i = 0; i < 32; i += 8)
        dst[(size_t)(c0 + y + i) * R + r0 + x] = __float2half_rn(tile[x][y + i]);
}

// ============================ transpose V (fp16) ===========================
// g_v [bh][s][dh] -> g_vT [bh][dh][s]
__global__ void transpose_v_kernel() {
    __shared__ __half tile[32][33];
    int z = blockIdx.z;
    const __half* src = g_v + (size_t)z * S_ * DH_;
    __half* dst = g_vT + (size_t)z * S_ * DH_;
    int s0 = blockIdx.y * 32, d0 = blockIdx.x * 32;
    int x = threadIdx.x, y = threadIdx.y;
    #pragma unroll
    for (int i = 0; i < 32; i += 8)
        tile[y + i][x] = src[(size_t)(s0 + y + i) * DH_ + d0 + x];
    __syncthreads();
    #pragma unroll
    for (int i = 0; i < 32; i += 8)
        dst[(size_t)(d0 + y + i) * S_ + s0 + x] = tile[x][y + i];
}

// ============================ gated expand (O), fp16 out ===================
__global__ __launch_bounds__(256) void expand_kernel() {
    int idx = blockIdx.x * 256 + threadIdx.x;   // 4096*32*32
    int dh4 = idx & 31;
    int he = (idx >> 5) & 31;
    int t = idx >> 10;
    int h = he >> 2;
    int b = t >> 11, s = t & (S_ - 1);
    float g = g_go[(size_t)t * GE_ + he];
    float4 r = *(const float4*)&g_res[(((size_t)b * H_ + h) * S_ + s) * DH_ + dh4 * 4];
    __half2 h0 = __floats2half2_rn(r.x * g, r.y * g);
    __half2 h1 = __floats2half2_rn(r.z * g, r.w * g);
    __half2* dst = (__half2*)&g_aexp[(size_t)t * KEXP_ + he * 128 + dh4 * 4];
    dst[0] = h0; dst[1] = h1;
}

// ============================ gated reduce (V), fp16 in/out ================
__global__ __launch_bounds__(256) void vgate_kernel() {
    int idx = blockIdx.x * 256 + threadIdx.x;   // 4096*8*32
    int dh4 = idx & 31;
    int h = (idx >> 5) & 7;
    int t = idx >> 8;
    int b = t >> 11, s = t & (S_ - 1);
    const __half2* y = (const __half2*)(g_yall + (size_t)t * KEXP_ + h * 512) + dh4 * 2;
    const float* g = g_gv + (size_t)t * GE_ + h * 4;
    float2 a0 = make_float2(0.f, 0.f), a1 = make_float2(0.f, 0.f);
    #pragma unroll
    for (int e = 0; e < 4; e++) {
        float ge = g[e];
        float2 y0 = __half22float2(y[e * 64 + 0]);
        float2 y1 = __half22float2(y[e * 64 + 1]);
        a0.x += ge * y0.x; a0.y += ge * y0.y;
        a1.x += ge * y1.x; a1.y += ge * y1.y;
    }
    __half2* dst = (__half2*)&g_v[(((size_t)b * H_ + h) * S_ + s) * DH_ + dh4 * 4];
    dst[0] = __floats2half2_rn(a0.x, a0.y);
    dst[1] = __floats2half2_rn(a1.x, a1.y);
}

// ============================ fp16 mma GEMM (cp.async, 512 thr) ============
// MODE 0: fp32 row-major C.  MODE 1: qk merged, fp16 C [B,H,S,DH].
// MODE 2: fp16 row-major C.
#define PADH_ 36
#define ABUF_ (128 * PADH_)
#define BBUF_ (256 * PADH_)
#define STG_W (ABUF_ + BBUF_)
#define GSMEM_BYTES (3 * STG_W * 4)     // 165888

template<int MODE>
__global__ __launch_bounds__(512) void gemm_f16(const __half* __restrict__ A,
                                                const __half* __restrict__ B,
                                                void* __restrict__ Cv,
                                                int Ktot, int ldc, float alpha,
                                                const __half* __restrict__ A2,
                                                const __half* __restrict__ B2,
                                                void* __restrict__ C2v) {
    extern __shared__ __align__(16) uint32_t dsm[];
    uint32_t sbase = smem_u32(dsm);

    int tid = threadIdx.x;
    int wid = tid >> 5;
    int lane = tid & 31;
    int m0 = blockIdx.y * 128, n0 = blockIdx.x * 256;
    int m0w = (wid >> 2) * 32, n0w = (wid & 3) * 64;

    void* Cp = Cv;
    if (MODE == 1 && blockIdx.z == 1) { A = A2; B = B2; Cp = C2v; }

    int ar0 = tid >> 3, ao0 = (tid & 7) * 8;
    int aS1 = tid + 512;
    int ar1 = aS1 >> 3, ao1 = (aS1 & 7) * 8;
    const __half* Asrc0 = A + (size_t)(m0 + ar0) * Ktot + ao0;
    const __half* Asrc1 = A + (size_t)(m0 + ar1) * Ktot + ao1;
    uint32_t aDst0 = (uint32_t)(ar0 * PADH_ + (ao0 >> 1)) * 4;
    uint32_t aDst1 = (uint32_t)(ar1 * PADH_ + (ao1 >> 1)) * 4;
    const __half* Bsrc[4];
    uint32_t bDst[4];
    #pragma unroll
    for (int j = 0; j < 4; j++) {
        int s = tid + 512 * j;
        int brr = s >> 3, bo = (s & 7) * 8;
        Bsrc[j] = B + (size_t)(n0 + brr) * Ktot + bo;
        bDst[j] = (uint32_t)(ABUF_ + brr * PADH_ + (bo >> 1)) * 4;
    }

    float acc[2][8][4];
    #pragma unroll
    for (int i = 0; i < 2; i++)
        #pragma unroll
        for (int j = 0; j < 8; j++)
            #pragma unroll
            for (int c = 0; c < 4; c++) acc[i][j][c] = 0.f;

    int KT = Ktot >> 6;

    auto copyTile = [&](int kt, int stg) {
        uint32_t so = sbase + (uint32_t)(stg * STG_W * 4);
        int ko = kt * 64;
        CP16(so + aDst0, Asrc0 + ko);
        CP16(so + aDst1, Asrc1 + ko);
        #pragma unroll
        for (int j = 0; j < 4; j++)
            CP16(so + bDst[j], Bsrc[j] + ko);
        CP_COMMIT();
    };

    copyTile(0, 0);
    copyTile(1, 1);

    int r4 = lane >> 2, c4 = lane & 3;

    for (int kt = 0; kt < KT; kt++) {
        if (kt + 1 < KT) CP_WAIT1(); else CP_WAIT0();
        __syncthreads();

        uint32_t* As = dsm + (kt % 3) * STG_W;
        uint32_t* Bs = As + ABUF_;
        #pragma unroll
        for (int ks = 0; ks < 4; ks++) {
            int kb = ks * 8;
            uint32_t a[2][4], b[8][2];
            #pragma unroll
            for (int mi = 0; mi < 2; mi++) {
                int rr = (m0w + mi * 16 + r4) * PADH_ + kb + c4;
                a[mi][0] = As[rr];
                a[mi][1] = As[rr + 8 * PADH_];
                a[mi][2] = As[rr + 4];
                a[mi][3] = As[rr + 8 * PADH_ + 4];
            }
            #pragma unroll
            for (int ni = 0; ni < 8; ni++) {
                int rr = (n0w + ni * 8 + r4) * PADH_ + kb + c4;
                b[ni][0] = Bs[rr];
                b[ni][1] = Bs[rr + 4];
            }
            #pragma unroll
            for (int mi = 0; mi < 2; mi++)
                #pragma unroll
                for (int ni = 0; ni < 8; ni++)
                    mma_f16(acc[mi][ni], a[mi], b[ni]);
        }

        if (kt + 2 < KT) copyTile(kt + 2, (kt + 2) % 3);
    }

    #pragma unroll
    for (int mi = 0; mi < 2; mi++) {
        #pragma unroll
        for (int half_m = 0; half_m < 2; half_m++) {
            int m = m0 + m0w + mi * 16 + half_m * 8 + r4;
            int bb = m >> 11, ss = m & (S_ - 1);
            #pragma unroll
            for (int ni = 0; ni < 8; ni++) {
                int n = n0 + n0w + ni * 8 + c4 * 2;
                float ox = acc[mi][ni][half_m * 2 + 0] * alpha;
                float oy = acc[mi][ni][half_m * 2 + 1] * alpha;
                if (MODE == 1) {
                    int h = n >> 7, dh = n & 127;
                    *(__half2*)((__half*)Cp + (((size_t)bb * H_ + h) * S_ + ss) * DH_ + dh) =
                        __floats2half2_rn(ox, oy);
                } else if (MODE == 2) {
                    *(__half2*)((__half*)Cp + (size_t)m * ldc + n) = __floats2half2_rn(ox, oy);
                } else {
                    *(float2*)((float*)Cp + (size_t)m * ldc + n) = make_float2(ox, oy);
                }
            }
        }
    }
}

// ============================ fp16 flash attention =========================
// 256 thr, q tile 128 (8 warps x 16 rows), kv tile 128, cp.async dbl-buffered
// K (kv-major) and V (dh-major from g_vT).  Tiles: rows of 64 words pad 68.
#define APH_ 68
#define ATILE_ (128 * APH_)             // words per tile
#define QS_OFF 0
#define KS_OFF ATILE_
#define VT_OFF (3 * ATILE_)
#define PS_OFF (5 * ATILE_)
#define ATTN_SMEM (6 * ATILE_ * 4)      // 208896

__global__ __launch_bounds__(256) void attn_tc_kernel() {
    extern __shared__ __align__(16) uint32_t asm_[];
    uint32_t sbase = smem_u32(asm_);
    uint32_t* Qs = asm_ + QS_OFF;
    uint32_t* Ps = asm_ + PS_OFF;

    int bh = blockIdx.y;
    int q0 = blockIdx.x * 128;
    const __half* Qg = g_q + (size_t)bh * S_ * DH_;
    const __half* Kg = g_k + (size_t)bh * S_ * DH_;
    const __half* VTg = g_vT + (size_t)bh * S_ * DH_;   // [dh][s]

    int tid = threadIdx.x;
    int wid = tid >> 5;
    int lane = tid & 31;
    int r4 = lane >> 2, c4 = lane & 3;
    int m0w = wid * 16;

    // load Q: 128 rows x 128 halves
    for (int i = tid; i < 2048; i += 256) {
        int r = i >> 4, w = i & 15;
        *(uint4*)&Qs[r * APH_ + w * 4] = *(const uint4*)(Qg + (size_t)(q0 + r) * DH_ + w * 8);
    }

    auto copyKV = [&](int j0, int buf) {
        uint32_t ks = sbase + (uint32_t)((KS_OFF + buf * ATILE_) * 4);
        uint32_t vs = sbase + (uint32_t)((VT_OFF + buf * ATILE_) * 4);
        #pragma unroll
        for (int jj = 0; jj < 8; jj++) {
            int i = tid + 256 * jj;
            int r = i >> 4, w = i & 15;
            CP16(ks + (uint32_t)(r * APH_ + w * 4) * 4, Kg + (size_t)(j0 + r) * DH_ + w * 8);
            CP16(vs + (uint32_t)(r * APH_ + w * 4) * 4, VTg + (size_t)r * S_ + j0 + w * 8);
        }
        CP_COMMIT();
    };

    copyKV(0, 0);

    float o[16][4];
    #pragma unroll
    for (int ni = 0; ni < 16; ni++)
        #pragma unroll
        for (int c = 0; c < 4; c++) o[ni][c] = 0.f;
    float mA = -1e30f, mB = -1e30f, lA = 0.f, lB = 0.f;

    for (int it = 0; it < S_ / 128; it++) {
        int buf = it & 1;
        __syncthreads();    // all done reading buf^1 (prev compute); Q visible it=0
        if (it + 1 < S_ / 128) {
            copyKV((it + 1) * 128, buf ^ 1);
            CP_WAIT1();
        } else {
            CP_WAIT0();
        }
        __syncthreads();    // tile it visible to all

        uint32_t* Ks = asm_ + KS_OFF + buf * ATILE_;
        uint32_t* Vt = asm_ + VT_OFF + buf * ATILE_;

        // S = Q K^T  (16q x 128kv per warp)
        float sf[16][4];
        #pragma unroll
        for (int ni = 0; ni < 16; ni++)
            #pragma unroll
            for (int c = 0; c < 4; c++) sf[ni][c] = 0.f;

        #pragma unroll
        for (int ks = 0; ks < 8; ks++) {
            int kb = ks * 8;
            uint32_t a[4];
            int ar = (m0w + r4) * APH_ + kb + c4;
            a[0] = Qs[ar];
            a[1] = Qs[ar + 8 * APH_];
            a[2] = Qs[ar + 4];
            a[3] = Qs[ar + 8 * APH_ + 4];
            #pragma unroll
            for (int ni = 0; ni < 16; ni++) {
                uint32_t b[2];
                int br = (ni * 8 + r4) * APH_ + kb + c4;
                b[0] = Ks[br];
                b[1] = Ks[br + 4];
                mma_f16(sf[ni], a, b);
            }
        }

        float mxA = -1e30f, mxB = -1e30f;
        #pragma unroll
        for (int ni = 0; ni < 16; ni++) {
            mxA = fmaxf(mxA, fmaxf(sf[ni][0], sf[ni][1]));
            mxB = fmaxf(mxB, fmaxf(sf[ni][2], sf[ni][3]));
        }
        mxA = fmaxf(mxA, __shfl_xor_sync(0xffffffffu, mxA, 1));
        mxA = fmaxf(mxA, __shfl_xor_sync(0xffffffffu, mxA, 2));
        mxB = fmaxf(mxB, __shfl_xor_sync(0xffffffffu, mxB, 1));
        mxB = fmaxf(mxB, __shfl_xor_sync(0xffffffffu, mxB, 2));
        float mnA = fmaxf(mA, mxA), mnB = fmaxf(mB, mxB);
        float scA = __expf(mA - mnA), scB = __expf(mB - mnB);
        float sA = 0.f, sB = 0.f;
        int prA = (m0w + r4) * APH_;
        int prB = prA + 8 * APH_;
        #pragma unroll
        for (int ni = 0; ni < 16; ni++) {
            float e0 = __expf(sf[ni][0] - mnA);
            float e1 = __expf(sf[ni][1] - mnA);
            float e2 = __expf(sf[ni][2] - mnB);
            float e3 = __expf(sf[ni][3] - mnB);
            sA += e0 + e1; sB += e2 + e3;
            int cw = ni * 4 + c4;
            Ps[prA + cw] = pack_h2(e0, e1);
            Ps[prB + cw] = pack_h2(e2, e3);
        }
        sA += __shfl_xor_sync(0xffffffffu, sA, 1);
        sA += __shfl_xor_sync(0xffffffffu, sA, 2);
        sB += __shfl_xor_sync(0xffffffffu, sB, 1);
        sB += __shfl_xor_sync(0xffffffffu, sB, 2);
        lA = lA * scA + sA; lB = lB * scB + sB;
        mA = mnA; mB = mnB;
        #pragma unroll
        for (int ni = 0; ni < 16; ni++) {
            o[ni][0] *= scA; o[ni][1] *= scA;
            o[ni][2] *= scB; o[ni][3] *= scB;
        }
        __syncwarp();   // Ps rows warp-private

        // O += P V  (K = 128 kv halves -> 8 steps; 128 dh cols)
        #pragma unroll
        for (int ks = 0; ks < 8; ks++) {
            int kb = ks * 8;
            uint32_t a[4];
            int ar = (m0w + r4) * APH_ + kb + c4;
            a[0] = Ps[ar];
            a[1] = Ps[ar + 8 * APH_];
            a[2] = Ps[ar + 4];
            a[3] = Ps[ar + 8 * APH_ + 4];
            #pragma unroll
            for (int ni = 0; ni < 16; ni++) {
                uint32_t b[2];
                int br = (ni * 8 + r4) * APH_ + kb + c4;
                b[0] = Vt[br];
                b[1] = Vt[br + 4];
                mma_f16(o[ni], a, b);
            }
        }
    }

    float invA = 1.f / lA, invB = 1.f / lB;
    int rA = q0 + m0w + r4;
    float* OgA = g_res + (size_t)bh * S_ * DH_ + (size_t)rA * DH_;
    float* OgB = OgA + 8 * DH_;
    #pragma unroll
    for (int ni = 0; ni < 16; ni++) {
        int cc = ni * 8 + c4 * 2;
        float2 oa, ob;
        oa.x = o[ni][0] * invA; oa.y = o[ni][1] * invA;
        ob.x = o[ni][2] * invB; ob.y = o[ni][3] * invB;
        *(float2*)(OgA + cc) = oa;
        *(float2*)(OgB + cc) = ob;
    }
}

// ---------------------------------------------------------------------------
extern "C" void kernel_launch(void* const* d_in, const int* in_sizes, int n_in,
                              void* d_out, int out_size) {
    const float* q_src = (const float*)d_in[0];
    const float* k_src = (const float*)d_in[1];
    const float* v_src = (const float*)d_in[2];
    const float* Wq    = (const float*)d_in[3];
    const float* Wk    = (const float*)d_in[4];
    const float* Wv    = (const float*)d_in[5];
    const float* Wo    = (const float*)d_in[6];
    const float* sel_v = (const float*)d_in[7];
    const float* sel_o = (const float*)d_in[8];
    float* outp = (float*)d_out;

    cudaFuncSetAttribute(attn_tc_kernel, cudaFuncAttributeMaxDynamicSharedMemorySize, ATTN_SMEM);
    cudaFuncSetAttribute(gemm_f16<0>, cudaFuncAttributeMaxDynamicSharedMemorySize, GSMEM_BYTES);
    cudaFuncSetAttribute(gemm_f16<1>, cudaFuncAttributeMaxDynamicSharedMemorySize, GSMEM_BYTES);
    cudaFuncSetAttribute(gemm_f16<2>, cudaFuncAttributeMaxDynamicSharedMemorySize, GSMEM_BYTES);

    __half *gq, *gk, *gyall, *gaexp, *gwvT, *gwoT, *gqc, *gkc, *gvc, *gwqc, *gwkc;
    cudaGetSymbolAddress((void**)&gq, g_q);
    cudaGetSymbolAddress((void**)&gk, g_k);
    cudaGetSymbolAddress((void**)&gyall, g_yall);
    cudaGetSymbolAddress((void**)&gaexp, g_aexp);
    cudaGetSymbolAddress((void**)&gwvT, g_wvT);
    cudaGetSymbolAddress((void**)&gwoT, g_woT);
    cudaGetSymbolAddress((void**)&gqc, g_qc);
    cudaGetSymbolAddress((void**)&gkc, g_kc);
    cudaGetSymbolAddress((void**)&gvc, g_vc);
    cudaGetSymbolAddress((void**)&gwqc, g_wqc);
    cudaGetSymbolAddress((void**)&gwkc, g_wkc);

    const float scale = 0.29730177875068026f;  // 128^-0.25

    router_kernel<<<TOK_, 256>>>(q_src, k_src, sel_v, sel_o);

    int n4a = TOK_ * D_ / 4, n4w = D_ * D_ / 4;
    conv_kernel<<<(n4a + 255) / 256, 256>>>(q_src, gqc, n4a);
    conv_kernel<<<(n4a + 255) / 256, 256>>>(k_src, gkc, n4a);
    conv_kernel<<<(n4a + 255) / 256, 256>>>(v_src, gvc, n4a);
    conv_kernel<<<(n4w + 255) / 256, 256>>>(Wq, gwqc, n4w);
    conv_kernel<<<(n4w + 255) / 256, 256>>>(Wk, gwkc, n4w);

    transpose_kernel<<<dim3(DH_ / 32, D_ / 32, GE_), dim3(32, 8)>>>(Wv, gwvT, D_, DH_);
    transpose_kernel<<<dim3(D_ / 32, KEXP_ / 32, 1), dim3(32, 8)>>>(Wo, gwoT, KEXP_, D_);

    // merged q/k projections: M=4096, N=1024, K=1024; z=0 -> q, z=1 -> k
    gemm_f16<1><<<dim3(D_ / 256, TOK_ / 128, 2), 512, GSMEM_BYTES>>>(
        gqc, gwqc, gq, D_, 0, scale, gkc, gwkc, gk);

    // all-expert V: M=4096, N=4096, K=1024 -> fp16 yall
    gemm_f16<2><<<dim3(KEXP_ / 256, TOK_ / 128), 512, GSMEM_BYTES>>>(
        gvc, gwvT, gyall, D_, KEXP_, 1.0f, nullptr, nullptr, nullptr);
    vgate_kernel<<<TOK_ * H_ * 32 / 256, 256>>>();
    transpose_v_kernel<<<dim3(DH_ / 32, S_ / 32, B_ * H_), dim3(32, 8)>>>();

    attn_tc_kernel<<<dim3(S_ / 128, B_ * H_), 256, ATTN_SMEM>>>();

    expand_kernel<<<TOK_ * GE_ * 32 / 256, 256>>>();
    // out: M=4096, N=1024, K=4096 -> fp32
    gemm_f16<0><<<dim3(D_ / 256, TOK_ / 128), 512, GSMEM_BYTES>>>(
        gaexp, gwoT, outp, KEXP_, D_, 1.0f, nullptr, nullptr, nullptr);
}

// round 13
// speedup vs baseline: 1.9356x; 1.0848x over previous
#include <cuda_runtime.h>
#include <cuda_fp16.h>
#include <math.h>
#include <stdint.h>

// ---------------------------------------------------------------------------
// SwitchHeadCore: B=2,S=2048,D=1024,H=8,E=4,K=2,DH=128
// fp16 m16n8k16 everywhere (fp32 accum). cp.async GEMMs; fp32 blocked router
// (32 tokens/block, exact top-k); attention kv-tile 128 cp.async dbl-buffer.
// ---------------------------------------------------------------------------

#define B_ 2
#define S_ 2048
#define D_ 1024
#define H_ 8
#define E_ 4
#define DH_ 128
#define TOK_ (B_ * S_)              // 4096
#define GE_ (H_ * E_)               // 32
#define KEXP_ 4096                  // H*E*DH

__device__ __align__(16) __half g_q[TOK_ * D_];     // [B,H,S,DH]
__device__ __align__(16) __half g_k[TOK_ * D_];
__device__ __align__(16) __half g_v[TOK_ * D_];     // [B,H,S,DH]
__device__ __align__(16) __half g_vT[TOK_ * D_];    // [B,H,DH,S]
__device__ __align__(16) float  g_res[TOK_ * D_];   // fp32
__device__ float g_gv[TOK_ * GE_];
__device__ float g_go[TOK_ * GE_];
__device__ __align__(16) __half g_yall[(size_t)TOK_ * KEXP_];
__device__ __align__(16) __half g_aexp[(size_t)TOK_ * KEXP_];
__device__ __align__(16) __half g_wvT[(size_t)KEXP_ * D_];    // [(h,e,dh), d]
__device__ __align__(16) __half g_woT[(size_t)D_ * KEXP_];    // [o, (h,e,dh)]
__device__ __align__(16) __half g_qc[TOK_ * D_];
__device__ __align__(16) __half g_kc[TOK_ * D_];
__device__ __align__(16) __half g_vc[TOK_ * D_];
__device__ __align__(16) __half g_wqc[D_ * D_];
__device__ __align__(16) __half g_wkc[D_ * D_];

// ============================ helpers ======================================
__device__ __forceinline__ void mma_f16(float* d, const uint32_t* a, const uint32_t* b) {
    asm volatile(
        "mma.sync.aligned.m16n8k16.row.col.f32.f16.f16.f32 "
        "{%0,%1,%2,%3}, {%4,%5,%6,%7}, {%8,%9}, {%0,%1,%2,%3};\n"
        : "+f"(d[0]), "+f"(d[1]), "+f"(d[2]), "+f"(d[3])
        : "r"(a[0]), "r"(a[1]), "r"(a[2]), "r"(a[3]), "r"(b[0]), "r"(b[1]));
}
__device__ __forceinline__ uint32_t smem_u32(const void* p) {
    uint32_t a;
    asm("{ .reg .u64 t; cvta.to.shared.u64 t, %1; cvt.u32.u64 %0, t; }" : "=r"(a) : "l"(p));
    return a;
}
__device__ __forceinline__ uint32_t pack_h2(float x, float y) {
    __half2 h = __floats2half2_rn(x, y);
    return *(uint32_t*)&h;
}
#define CP16(dst, src) \
    asm volatile("cp.async.cg.shared.global [%0], [%1], 16;" :: "r"(dst), "l"(src))
#define CP_COMMIT() asm volatile("cp.async.commit_group;")
#define CP_WAIT1() asm volatile("cp.async.wait_group 1;")
#define CP_WAIT0() asm volatile("cp.async.wait_group 0;")

// ============================ blocked fp32 router ==========================
// 32 tokens per block, 256 threads.  xs cached in SMEM (pad 1033 words to
// avoid 8-way LDS conflicts); sel streamed once per block.  Exact fp32 dots
// -> top-k selection identical to the reference.
#define RT_ 32
#define RXP_ 1033
#define RSMEM_BYTES ((RT_ * RXP_ + RT_ * GE_) * 4)   // 136320

__global__ __launch_bounds__(256) void router_kernel(const float* __restrict__ k_src,
                                                     const float* __restrict__ q_src,
                                                     const float* __restrict__ sel_v,
                                                     const float* __restrict__ sel_o) {
    extern __shared__ float rsm[];
    float* xs = rsm;                    // [RT_][RXP_]
    float* sg = rsm + RT_ * RXP_;       // [RT_][GE_]

    int z = blockIdx.y;
    const float* xsrc = z ? q_src : k_src;
    const float* sel  = z ? sel_o : sel_v;
    float* gout       = z ? g_go  : g_gv;

    int t0 = blockIdx.x * RT_;
    int tid = threadIdx.x;

    // load 32 token rows (float4)
    for (int i = tid; i < RT_ * (D_ / 4); i += 256) {
        int r = i >> 8, c4 = i & 255;
        float4 v = ((const float4*)(xsrc + (size_t)(t0 + r) * D_))[c4];
        float* dst = xs + r * RXP_ + c4 * 4;
        dst[0] = v.x; dst[1] = v.y; dst[2] = v.z; dst[3] = v.w;
    }
    __syncthreads();

    int g = tid >> 3, slot = tid & 7;
    const float* w = sel + (size_t)g * D_;
    const float* x0 = xs + (slot * 4 + 0) * RXP_;
    const float* x1 = xs + (slot * 4 + 1) * RXP_;
    const float* x2 = xs + (slot * 4 + 2) * RXP_;
    const float* x3 = xs + (slot * 4 + 3) * RXP_;
    float s0 = 0.f, s1 = 0.f, s2 = 0.f, s3 = 0.f;
    #pragma unroll 4
    for (int d = 0; d < D_; d++) {
        float sv = w[d];
        s0 += x0[d] * sv;
        s1 += x1[d] * sv;
        s2 += x2[d] * sv;
        s3 += x3[d] * sv;
    }
    sg[(slot * 4 + 0) * GE_ + g] = s0;
    sg[(slot * 4 + 1) * GE_ + g] = s1;
    sg[(slot * 4 + 2) * GE_ + g] = s2;
    sg[(slot * 4 + 3) * GE_ + g] = s3;
    __syncthreads();

    // top-2 per (token, head): 256 threads = 32 tokens x 8 heads
    int t = tid >> 3, h = tid & 7;
    float vals[4];
    #pragma unroll
    for (int e = 0; e < 4; e++)
        vals[e] = 1.f / (1.f + __expf(-sg[t * GE_ + h * 4 + e]));
    int i1 = 0;
    #pragma unroll
    for (int e = 1; e < 4; e++) if (vals[e] > vals[i1]) i1 = e;
    int i2 = -1;
    #pragma unroll
    for (int e = 0; e < 4; e++) {
        if (e == i1) continue;
        if (i2 < 0 || vals[e] > vals[i2]) i2 = e;
    }
    #pragma unroll
    for (int e = 0; e < 4; e++)
        gout[(size_t)(t0 + t) * GE_ + h * 4 + e] = (e == i1 || e == i2) ? vals[e] : 0.f;
}

// ============================ convert (fp32 -> fp16) =======================
__global__ void conv_kernel(const float* __restrict__ src, __half* __restrict__ dst, int n4) {
    int i = blockIdx.x * blockDim.x + threadIdx.x;
    if (i >= n4) return;
    float4 v = ((const float4*)src)[i];
    ((__half2*)dst)[i * 2 + 0] = __floats2half2_rn(v.x, v.y);
    ((__half2*)dst)[i * 2 + 1] = __floats2half2_rn(v.z, v.w);
}

// ============================ transpose (fp32 src -> fp16 dst) =============
__global__ void transpose_kernel(const float* __restrict__ src, __half* __restrict__ dst,
                                 int R, int C) {
    __shared__ float tile[32][33];
    size_t zo = (size_t)blockIdx.z * R * C;
    src += zo; dst += zo;
    int r0 = blockIdx.y * 32, c0 = blockIdx.x * 32;
    int x = threadIdx.x, y = threadIdx.y;
    #pragma unroll
    for (int i = 0; i < 32; i += 8)
        tile[y + i][x] = src[(size_t)(r0 + y + i) * C + c0 + x];
    __syncthreads();
    #pragma unroll
    for (int i = 0; i < 32; i += 8)
        dst[(size_t)(c0 + y + i) * R + r0 + x] = __float2half_rn(tile[x][y + i]);
}

// ============================ transpose V (fp16) ===========================
__global__ void transpose_v_kernel() {
    __shared__ __half tile[32][33];
    int z = blockIdx.z;
    const __half* src = g_v + (size_t)z * S_ * DH_;
    __half* dst = g_vT + (size_t)z * S_ * DH_;
    int s0 = blockIdx.y * 32, d0 = blockIdx.x * 32;
    int x = threadIdx.x, y = threadIdx.y;
    #pragma unroll
    for (int i = 0; i < 32; i += 8)
        tile[y + i][x] = src[(size_t)(s0 + y + i) * DH_ + d0 + x];
    __syncthreads();
    #pragma unroll
    for (int i = 0; i < 32; i += 8)
        dst[(size_t)(d0 + y + i) * S_ + s0 + x] = tile[x][y + i];
}

// ============================ gated expand (O), fp16 out ===================
__global__ __launch_bounds__(256) void expand_kernel() {
    int idx = blockIdx.x * 256 + threadIdx.x;   // 4096*32*32
    int dh4 = idx & 31;
    int he = (idx >> 5) & 31;
    int t = idx >> 10;
    int h = he >> 2;
    int b = t >> 11, s = t & (S_ - 1);
    float g = g_go[(size_t)t * GE_ + he];
    float4 r = *(const float4*)&g_res[(((size_t)b * H_ + h) * S_ + s) * DH_ + dh4 * 4];
    __half2* dst = (__half2*)&g_aexp[(size_t)t * KEXP_ + he * 128 + dh4 * 4];
    dst[0] = __floats2half2_rn(r.x * g, r.y * g);
    dst[1] = __floats2half2_rn(r.z * g, r.w * g);
}

// ============================ gated reduce (V), fp16 in/out ================
__global__ __launch_bounds__(256) void vgate_kernel() {
    int idx = blockIdx.x * 256 + threadIdx.x;   // 4096*8*32
    int dh4 = idx & 31;
    int h = (idx >> 5) & 7;
    int t = idx >> 8;
    int b = t >> 11, s = t & (S_ - 1);
    const __half2* y = (const __half2*)(g_yall + (size_t)t * KEXP_ + h * 512) + dh4 * 2;
    const float* g = g_gv + (size_t)t * GE_ + h * 4;
    float2 a0 = make_float2(0.f, 0.f), a1 = make_float2(0.f, 0.f);
    #pragma unroll
    for (int e = 0; e < 4; e++) {
        float ge = g[e];
        float2 y0 = __half22float2(y[e * 64 + 0]);
        float2 y1 = __half22float2(y[e * 64 + 1]);
        a0.x += ge * y0.x; a0.y += ge * y0.y;
        a1.x += ge * y1.x; a1.y += ge * y1.y;
    }
    __half2* dst = (__half2*)&g_v[(((size_t)b * H_ + h) * S_ + s) * DH_ + dh4 * 4];
    dst[0] = __floats2half2_rn(a0.x, a0.y);
    dst[1] = __floats2half2_rn(a1.x, a1.y);
}

// ============================ fp16 mma GEMM (cp.async, 512 thr) ============
// MODE 0: fp32 row-major C.  MODE 1: qk merged, fp16 C [B,H,S,DH].
// MODE 2: fp16 row-major C.
#define PADH_ 36
#define ABUF_ (128 * PADH_)
#define BBUF_ (256 * PADH_)
#define STG_W (ABUF_ + BBUF_)
#define GSMEM_BYTES (3 * STG_W * 4)     // 165888

template<int MODE>
__global__ __launch_bounds__(512) void gemm_f16(const __half* __restrict__ A,
                                                const __half* __restrict__ B,
                                                void* __restrict__ Cv,
                                                int Ktot, int ldc, float alpha,
                                                const __half* __restrict__ A2,
                                                const __half* __restrict__ B2,
                                                void* __restrict__ C2v) {
    extern __shared__ __align__(16) uint32_t dsm[];
    uint32_t sbase = smem_u32(dsm);

    int tid = threadIdx.x;
    int wid = tid >> 5;
    int lane = tid & 31;
    int m0 = blockIdx.y * 128, n0 = blockIdx.x * 256;
    int m0w = (wid >> 2) * 32, n0w = (wid & 3) * 64;

    void* Cp = Cv;
    if (MODE == 1 && blockIdx.z == 1) { A = A2; B = B2; Cp = C2v; }

    int ar0 = tid >> 3, ao0 = (tid & 7) * 8;
    int aS1 = tid + 512;
    int ar1 = aS1 >> 3, ao1 = (aS1 & 7) * 8;
    const __half* Asrc0 = A + (size_t)(m0 + ar0) * Ktot + ao0;
    const __half* Asrc1 = A + (size_t)(m0 + ar1) * Ktot + ao1;
    uint32_t aDst0 = (uint32_t)(ar0 * PADH_ + (ao0 >> 1)) * 4;
    uint32_t aDst1 = (uint32_t)(ar1 * PADH_ + (ao1 >> 1)) * 4;
    const __half* Bsrc[4];
    uint32_t bDst[4];
    #pragma unroll
    for (int j = 0; j < 4; j++) {
        int s = tid + 512 * j;
        int brr = s >> 3, bo = (s & 7) * 8;
        Bsrc[j] = B + (size_t)(n0 + brr) * Ktot + bo;
        bDst[j] = (uint32_t)(ABUF_ + brr * PADH_ + (bo >> 1)) * 4;
    }

    float acc[2][8][4];
    #pragma unroll
    for (int i = 0; i < 2; i++)
        #pragma unroll
        for (int j = 0; j < 8; j++)
            #pragma unroll
            for (int c = 0; c < 4; c++) acc[i][j][c] = 0.f;

    int KT = Ktot >> 6;

    auto copyTile = [&](int kt, int stg) {
        uint32_t so = sbase + (uint32_t)(stg * STG_W * 4);
        int ko = kt * 64;
        CP16(so + aDst0, Asrc0 + ko);
        CP16(so + aDst1, Asrc1 + ko);
        #pragma unroll
        for (int j = 0; j < 4; j++)
            CP16(so + bDst[j], Bsrc[j] + ko);
        CP_COMMIT();
    };

    copyTile(0, 0);
    copyTile(1, 1);

    int r4 = lane >> 2, c4 = lane & 3;

    for (int kt = 0; kt < KT; kt++) {
        if (kt + 1 < KT) CP_WAIT1(); else CP_WAIT0();
        __syncthreads();

        uint32_t* As = dsm + (kt % 3) * STG_W;
        uint32_t* Bs = As + ABUF_;
        #pragma unroll
        for (int ks = 0; ks < 4; ks++) {
            int kb = ks * 8;
            uint32_t a[2][4], b[8][2];
            #pragma unroll
            for (int mi = 0; mi < 2; mi++) {
                int rr = (m0w + mi * 16 + r4) * PADH_ + kb + c4;
                a[mi][0] = As[rr];
                a[mi][1] = As[rr + 8 * PADH_];
                a[mi][2] = As[rr + 4];
                a[mi][3] = As[rr + 8 * PADH_ + 4];
            }
            #pragma unroll
            for (int ni = 0; ni < 8; ni++) {
                int rr = (n0w + ni * 8 + r4) * PADH_ + kb + c4;
                b[ni][0] = Bs[rr];
                b[ni][1] = Bs[rr + 4];
            }
            #pragma unroll
            for (int mi = 0; mi < 2; mi++)
                #pragma unroll
                for (int ni = 0; ni < 8; ni++)
                    mma_f16(acc[mi][ni], a[mi], b[ni]);
        }

        if (kt + 2 < KT) copyTile(kt + 2, (kt + 2) % 3);
    }

    #pragma unroll
    for (int mi = 0; mi < 2; mi++) {
        #pragma unroll
        for (int half_m = 0; half_m < 2; half_m++) {
            int m = m0 + m0w + mi * 16 + half_m * 8 + r4;
            int bb = m >> 11, ss = m & (S_ - 1);
            #pragma unroll
            for (int ni = 0; ni < 8; ni++) {
                int n = n0 + n0w + ni * 8 + c4 * 2;
                float ox = acc[mi][ni][half_m * 2 + 0] * alpha;
                float oy = acc[mi][ni][half_m * 2 + 1] * alpha;
                if (MODE == 1) {
                    int h = n >> 7, dh = n & 127;
                    *(__half2*)((__half*)Cp + (((size_t)bb * H_ + h) * S_ + ss) * DH_ + dh) =
                        __floats2half2_rn(ox, oy);
                } else if (MODE == 2) {
                    *(__half2*)((__half*)Cp + (size_t)m * ldc + n) = __floats2half2_rn(ox, oy);
                } else {
                    *(float2*)((float*)Cp + (size_t)m * ldc + n) = make_float2(ox, oy);
                }
            }
        }
    }
}

// ============================ fp16 flash attention =========================
#define APH_ 68
#define ATILE_ (128 * APH_)
#define QS_OFF 0
#define KS_OFF ATILE_
#define VT_OFF (3 * ATILE_)
#define PS_OFF (5 * ATILE_)
#define ATTN_SMEM (6 * ATILE_ * 4)      // 208896

__global__ __launch_bounds__(256) void attn_tc_kernel() {
    extern __shared__ __align__(16) uint32_t asm_[];
    uint32_t sbase = smem_u32(asm_);
    uint32_t* Qs = asm_ + QS_OFF;
    uint32_t* Ps = asm_ + PS_OFF;

    int bh = blockIdx.y;
    int q0 = blockIdx.x * 128;
    const __half* Qg = g_q + (size_t)bh * S_ * DH_;
    const __half* Kg = g_k + (size_t)bh * S_ * DH_;
    const __half* VTg = g_vT + (size_t)bh * S_ * DH_;

    int tid = threadIdx.x;
    int wid = tid >> 5;
    int lane = tid & 31;
    int r4 = lane >> 2, c4 = lane & 3;
    int m0w = wid * 16;

    for (int i = tid; i < 2048; i += 256) {
        int r = i >> 4, w = i & 15;
        *(uint4*)&Qs[r * APH_ + w * 4] = *(const uint4*)(Qg + (size_t)(q0 + r) * DH_ + w * 8);
    }

    auto copyKV = [&](int j0, int buf) {
        uint32_t ks = sbase + (uint32_t)((KS_OFF + buf * ATILE_) * 4);
        uint32_t vs = sbase + (uint32_t)((VT_OFF + buf * ATILE_) * 4);
        #pragma unroll
        for (int jj = 0; jj < 8; jj++) {
            int i = tid + 256 * jj;
            int r = i >> 4, w = i & 15;
            CP16(ks + (uint32_t)(r * APH_ + w * 4) * 4, Kg + (size_t)(j0 + r) * DH_ + w * 8);
            CP16(vs + (uint32_t)(r * APH_ + w * 4) * 4, VTg + (size_t)r * S_ + j0 + w * 8);
        }
        CP_COMMIT();
    };

    copyKV(0, 0);

    float o[16][4];
    #pragma unroll
    for (int ni = 0; ni < 16; ni++)
        #pragma unroll
        for (int c = 0; c < 4; c++) o[ni][c] = 0.f;
    float mA = -1e30f, mB = -1e30f, lA = 0.f, lB = 0.f;

    for (int it = 0; it < S_ / 128; it++) {
        int buf = it & 1;
        __syncthreads();
        if (it + 1 < S_ / 128) {
            copyKV((it + 1) * 128, buf ^ 1);
            CP_WAIT1();
        } else {
            CP_WAIT0();
        }
        __syncthreads();

        uint32_t* Ks = asm_ + KS_OFF + buf * ATILE_;
        uint32_t* Vt = asm_ + VT_OFF + buf * ATILE_;

        float sf[16][4];
        #pragma unroll
        for (int ni = 0; ni < 16; ni++)
            #pragma unroll
            for (int c = 0; c < 4; c++) sf[ni][c] = 0.f;

        #pragma unroll
        for (int ks = 0; ks < 8; ks++) {
            int kb = ks * 8;
            uint32_t a[4];
            int ar = (m0w + r4) * APH_ + kb + c4;
            a[0] = Qs[ar];
            a[1] = Qs[ar + 8 * APH_];
            a[2] = Qs[ar + 4];
            a[3] = Qs[ar + 8 * APH_ + 4];
            #pragma unroll
            for (int ni = 0; ni < 16; ni++) {
                uint32_t b[2];
                int br = (ni * 8 + r4) * APH_ + kb + c4;
                b[0] = Ks[br];
                b[1] = Ks[br + 4];
                mma_f16(sf[ni], a, b);
            }
        }

        float mxA = -1e30f, mxB = -1e30f;
        #pragma unroll
        for (int ni = 0; ni < 16; ni++) {
            mxA = fmaxf(mxA, fmaxf(sf[ni][0], sf[ni][1]));
            mxB = fmaxf(mxB, fmaxf(sf[ni][2], sf[ni][3]));
        }
        mxA = fmaxf(mxA, __shfl_xor_sync(0xffffffffu, mxA, 1));
        mxA = fmaxf(mxA, __shfl_xor_sync(0xffffffffu, mxA, 2));
        mxB = fmaxf(mxB, __shfl_xor_sync(0xffffffffu, mxB, 1));
        mxB = fmaxf(mxB, __shfl_xor_sync(0xffffffffu, mxB, 2));
        float mnA = fmaxf(mA, mxA), mnB = fmaxf(mB, mxB);
        float scA = __expf(mA - mnA), scB = __expf(mB - mnB);
        float sA = 0.f, sB = 0.f;
        int prA = (m0w + r4) * APH_;
        int prB = prA + 8 * APH_;
        #pragma unroll
        for (int ni = 0; ni < 16; ni++) {
            float e0 = __expf(sf[ni][0] - mnA);
            float e1 = __expf(sf[ni][1] - mnA);
            float e2 = __expf(sf[ni][2] - mnB);
            float e3 = __expf(sf[ni][3] - mnB);
            sA += e0 + e1; sB += e2 + e3;
            int cw = ni * 4 + c4;
            Ps[prA + cw] = pack_h2(e0, e1);
            Ps[prB + cw] = pack_h2(e2, e3);
        }
        sA += __shfl_xor_sync(0xffffffffu, sA, 1);
        sA += __shfl_xor_sync(0xffffffffu, sA, 2);
        sB += __shfl_xor_sync(0xffffffffu, sB, 1);
        sB += __shfl_xor_sync(0xffffffffu, sB, 2);
        lA = lA * scA + sA; lB = lB * scB + sB;
        mA = mnA; mB = mnB;
        #pragma unroll
        for (int ni = 0; ni < 16; ni++) {
            o[ni][0] *= scA; o[ni][1] *= scA;
            o[ni][2] *= scB; o[ni][3] *= scB;
        }
        __syncwarp();

        #pragma unroll
        for (int ks = 0; ks < 8; ks++) {
            int kb = ks * 8;
            uint32_t a[4];
            int ar = (m0w + r4) * APH_ + kb + c4;
            a[0] = Ps[ar];
            a[1] = Ps[ar + 8 * APH_];
            a[2] = Ps[ar + 4];
            a[3] = Ps[ar + 8 * APH_ + 4];
            #pragma unroll
            for (int ni = 0; ni < 16; ni++) {
                uint32_t b[2];
                int br = (ni * 8 + r4) * APH_ + kb + c4;
                b[0] = Vt[br];
                b[1] = Vt[br + 4];
                mma_f16(o[ni], a, b);
            }
        }
    }

    float invA = 1.f / lA, invB = 1.f / lB;
    int rA = q0 + m0w + r4;
    float* OgA = g_res + (size_t)bh * S_ * DH_ + (size_t)rA * DH_;
    float* OgB = OgA + 8 * DH_;
    #pragma unroll
    for (int ni = 0; ni < 16; ni++) {
        int cc = ni * 8 + c4 * 2;
        float2 oa, ob;
        oa.x = o[ni][0] * invA; oa.y = o[ni][1] * invA;
        ob.x = o[ni][2] * invB; ob.y = o[ni][3] * invB;
        *(float2*)(OgA + cc) = oa;
        *(float2*)(OgB + cc) = ob;
    }
}

// ---------------------------------------------------------------------------
extern "C" void kernel_launch(void* const* d_in, const int* in_sizes, int n_in,
                              void* d_out, int out_size) {
    const float* q_src = (const float*)d_in[0];
    const float* k_src = (const float*)d_in[1];
    const float* v_src = (const float*)d_in[2];
    const float* Wq    = (const float*)d_in[3];
    const float* Wk    = (const float*)d_in[4];
    const float* Wv    = (const float*)d_in[5];
    const float* Wo    = (const float*)d_in[6];
    const float* sel_v = (const float*)d_in[7];
    const float* sel_o = (const float*)d_in[8];
    float* outp = (float*)d_out;

    cudaFuncSetAttribute(attn_tc_kernel, cudaFuncAttributeMaxDynamicSharedMemorySize, ATTN_SMEM);
    cudaFuncSetAttribute(gemm_f16<0>, cudaFuncAttributeMaxDynamicSharedMemorySize, GSMEM_BYTES);
    cudaFuncSetAttribute(gemm_f16<1>, cudaFuncAttributeMaxDynamicSharedMemorySize, GSMEM_BYTES);
    cudaFuncSetAttribute(gemm_f16<2>, cudaFuncAttributeMaxDynamicSharedMemorySize, GSMEM_BYTES);
    cudaFuncSetAttribute(router_kernel, cudaFuncAttributeMaxDynamicSharedMemorySize, RSMEM_BYTES);

    __half *gq, *gk, *gyall, *gaexp, *gwvT, *gwoT, *gqc, *gkc, *gvc, *gwqc, *gwkc;
    cudaGetSymbolAddress((void**)&gq, g_q);
    cudaGetSymbolAddress((void**)&gk, g_k);
    cudaGetSymbolAddress((void**)&gyall, g_yall);
    cudaGetSymbolAddress((void**)&gaexp, g_aexp);
    cudaGetSymbolAddress((void**)&gwvT, g_wvT);
    cudaGetSymbolAddress((void**)&gwoT, g_woT);
    cudaGetSymbolAddress((void**)&gqc, g_qc);
    cudaGetSymbolAddress((void**)&gkc, g_kc);
    cudaGetSymbolAddress((void**)&gvc, g_vc);
    cudaGetSymbolAddress((void**)&gwqc, g_wqc);
    cudaGetSymbolAddress((void**)&gwkc, g_wkc);

    const float scale = 0.29730177875068026f;  // 128^-0.25

    // fp32 blocked router (exact top-k)
    router_kernel<<<dim3(TOK_ / RT_, 2), 256, RSMEM_BYTES>>>(k_src, q_src, sel_v, sel_o);

    int n4a = TOK_ * D_ / 4, n4w = D_ * D_ / 4;
    conv_kernel<<<(n4a + 255) / 256, 256>>>(q_src, gqc, n4a);
    conv_kernel<<<(n4a + 255) / 256, 256>>>(k_src, gkc, n4a);
    conv_kernel<<<(n4a + 255) / 256, 256>>>(v_src, gvc, n4a);
    conv_kernel<<<(n4w + 255) / 256, 256>>>(Wq, gwqc, n4w);
    conv_kernel<<<(n4w + 255) / 256, 256>>>(Wk, gwkc, n4w);

    transpose_kernel<<<dim3(DH_ / 32, D_ / 32, GE_), dim3(32, 8)>>>(Wv, gwvT, D_, DH_);
    transpose_kernel<<<dim3(D_ / 32, KEXP_ / 32, 1), dim3(32, 8)>>>(Wo, gwoT, KEXP_, D_);

    // merged q/k projections: M=4096, N=1024, K=1024; z=0 -> q, z=1 -> k
    gemm_f16<1><<<dim3(D_ / 256, TOK_ / 128, 2), 512, GSMEM_BYTES>>>(
        gqc, gwqc, gq, D_, 0, scale, gkc, gwkc, gk);

    // all-expert V: M=4096, N=4096, K=1024 -> fp16 yall
    gemm_f16<2><<<dim3(KEXP_ / 256, TOK_ / 128), 512, GSMEM_BYTES>>>(
        gvc, gwvT, gyall, D_, KEXP_, 1.0f, nullptr, nullptr, nullptr);
    vgate_kernel<<<TOK_ * H_ * 32 / 256, 256>>>();
    transpose_v_kernel<<<dim3(DH_ / 32, S_ / 32, B_ * H_), dim3(32, 8)>>>();

    attn_tc_kernel<<<dim3(S_ / 128, B_ * H_), 256, ATTN_SMEM>>>();

    expand_kernel<<<TOK_ * GE_ * 32 / 256, 256>>>();
    // out: M=4096, N=1024, K=4096 -> fp32
    gemm_f16<0><<<dim3(D_ / 256, TOK_ / 128), 512, GSMEM_BYTES>>>(
        gaexp, gwoT, outp, KEXP_, D_, 1.0f, nullptr, nullptr, nullptr);
}

// round 14
// speedup vs baseline: 2.0086x; 1.0377x over previous
#include <cuda_runtime.h>
#include <cuda_fp16.h>
#include <math.h>
#include <stdint.h>

// ---------------------------------------------------------------------------
// SwitchHeadCore: B=2,S=2048,D=1024,H=8,E=4,K=2,DH=128
// fp16 m16n8k16 + ldmatrix fragment loads.  cp.async GEMMs; fp32 blocked
// router (exact top-k); attention kv-tile 128 cp.async double buffering.
// ---------------------------------------------------------------------------

#define B_ 2
#define S_ 2048
#define D_ 1024
#define H_ 8
#define E_ 4
#define DH_ 128
#define TOK_ (B_ * S_)              // 4096
#define GE_ (H_ * E_)               // 32
#define KEXP_ 4096                  // H*E*DH

__device__ __align__(16) __half g_q[TOK_ * D_];     // [B,H,S,DH]
__device__ __align__(16) __half g_k[TOK_ * D_];
__device__ __align__(16) __half g_v[TOK_ * D_];     // [B,H,S,DH]
__device__ __align__(16) __half g_vT[TOK_ * D_];    // [B,H,DH,S]
__device__ __align__(16) float  g_res[TOK_ * D_];   // fp32
__device__ float g_gv[TOK_ * GE_];
__device__ float g_go[TOK_ * GE_];
__device__ __align__(16) __half g_yall[(size_t)TOK_ * KEXP_];
__device__ __align__(16) __half g_aexp[(size_t)TOK_ * KEXP_];
__device__ __align__(16) __half g_wvT[(size_t)KEXP_ * D_];    // [(h,e,dh), d]
__device__ __align__(16) __half g_woT[(size_t)D_ * KEXP_];    // [o, (h,e,dh)]
__device__ __align__(16) __half g_qc[TOK_ * D_];
__device__ __align__(16) __half g_kc[TOK_ * D_];
__device__ __align__(16) __half g_vc[TOK_ * D_];
__device__ __align__(16) __half g_wqc[D_ * D_];
__device__ __align__(16) __half g_wkc[D_ * D_];

// ============================ helpers ======================================
__device__ __forceinline__ void mma_f16(float* d, const uint32_t* a, const uint32_t* b) {
    asm volatile(
        "mma.sync.aligned.m16n8k16.row.col.f32.f16.f16.f32 "
        "{%0,%1,%2,%3}, {%4,%5,%6,%7}, {%8,%9}, {%0,%1,%2,%3};\n"
        : "+f"(d[0]), "+f"(d[1]), "+f"(d[2]), "+f"(d[3])
        : "r"(a[0]), "r"(a[1]), "r"(a[2]), "r"(a[3]), "r"(b[0]), "r"(b[1]));
}
__device__ __forceinline__ void ldsm4(uint32_t addr, uint32_t* r) {
    asm volatile("ldmatrix.sync.aligned.m8n8.x4.shared.b16 {%0,%1,%2,%3}, [%4];"
        : "=r"(r[0]), "=r"(r[1]), "=r"(r[2]), "=r"(r[3]) : "r"(addr));
}
__device__ __forceinline__ uint32_t smem_u32(const void* p) {
    uint32_t a;
    asm("{ .reg .u64 t; cvta.to.shared.u64 t, %1; cvt.u32.u64 %0, t; }" : "=r"(a) : "l"(p));
    return a;
}
__device__ __forceinline__ uint32_t pack_h2(float x, float y) {
    __half2 h = __floats2half2_rn(x, y);
    return *(uint32_t*)&h;
}
#define CP16(dst, src) \
    asm volatile("cp.async.cg.shared.global [%0], [%1], 16;" :: "r"(dst), "l"(src))
#define CP_COMMIT() asm volatile("cp.async.commit_group;")
#define CP_WAIT1() asm volatile("cp.async.wait_group 1;")
#define CP_WAIT0() asm volatile("cp.async.wait_group 0;")

// ============================ blocked fp32 router ==========================
#define RT_ 32
#define RXP_ 1033
#define RSMEM_BYTES ((RT_ * RXP_ + RT_ * GE_) * 4)   // 136320

__global__ __launch_bounds__(256) void router_kernel(const float* __restrict__ k_src,
                                                     const float* __restrict__ q_src,
                                                     const float* __restrict__ sel_v,
                                                     const float* __restrict__ sel_o) {
    extern __shared__ float rsm[];
    float* xs = rsm;
    float* sg = rsm + RT_ * RXP_;

    int z = blockIdx.y;
    const float* xsrc = z ? q_src : k_src;
    const float* sel  = z ? sel_o : sel_v;
    float* gout       = z ? g_go  : g_gv;

    int t0 = blockIdx.x * RT_;
    int tid = threadIdx.x;

    for (int i = tid; i < RT_ * (D_ / 4); i += 256) {
        int r = i >> 8, c4 = i & 255;
        float4 v = ((const float4*)(xsrc + (size_t)(t0 + r) * D_))[c4];
        float* dst = xs + r * RXP_ + c4 * 4;
        dst[0] = v.x; dst[1] = v.y; dst[2] = v.z; dst[3] = v.w;
    }
    __syncthreads();

    int g = tid >> 3, slot = tid & 7;
    const float* w = sel + (size_t)g * D_;
    const float* x0 = xs + (slot * 4 + 0) * RXP_;
    const float* x1 = xs + (slot * 4 + 1) * RXP_;
    const float* x2 = xs + (slot * 4 + 2) * RXP_;
    const float* x3 = xs + (slot * 4 + 3) * RXP_;
    float s0 = 0.f, s1 = 0.f, s2 = 0.f, s3 = 0.f;
    #pragma unroll 4
    for (int d = 0; d < D_; d++) {
        float sv = w[d];
        s0 += x0[d] * sv;
        s1 += x1[d] * sv;
        s2 += x2[d] * sv;
        s3 += x3[d] * sv;
    }
    sg[(slot * 4 + 0) * GE_ + g] = s0;
    sg[(slot * 4 + 1) * GE_ + g] = s1;
    sg[(slot * 4 + 2) * GE_ + g] = s2;
    sg[(slot * 4 + 3) * GE_ + g] = s3;
    __syncthreads();

    int t = tid >> 3, h = tid & 7;
    float vals[4];
    #pragma unroll
    for (int e = 0; e < 4; e++)
        vals[e] = 1.f / (1.f + __expf(-sg[t * GE_ + h * 4 + e]));
    int i1 = 0;
    #pragma unroll
    for (int e = 1; e < 4; e++) if (vals[e] > vals[i1]) i1 = e;
    int i2 = -1;
    #pragma unroll
    for (int e = 0; e < 4; e++) {
        if (e == i1) continue;
        if (i2 < 0 || vals[e] > vals[i2]) i2 = e;
    }
    #pragma unroll
    for (int e = 0; e < 4; e++)
        gout[(size_t)(t0 + t) * GE_ + h * 4 + e] = (e == i1 || e == i2) ? vals[e] : 0.f;
}

// ============================ convert (fp32 -> fp16) =======================
__global__ void conv_kernel(const float* __restrict__ src, __half* __restrict__ dst, int n4) {
    int i = blockIdx.x * blockDim.x + threadIdx.x;
    if (i >= n4) return;
    float4 v = ((const float4*)src)[i];
    ((__half2*)dst)[i * 2 + 0] = __floats2half2_rn(v.x, v.y);
    ((__half2*)dst)[i * 2 + 1] = __floats2half2_rn(v.z, v.w);
}

// ============================ transpose (fp32 src -> fp16 dst) =============
__global__ void transpose_kernel(const float* __restrict__ src, __half* __restrict__ dst,
                                 int R, int C) {
    __shared__ float tile[32][33];
    size_t zo = (size_t)blockIdx.z * R * C;
    src += zo; dst += zo;
    int r0 = blockIdx.y * 32, c0 = blockIdx.x * 32;
    int x = threadIdx.x, y = threadIdx.y;
    #pragma unroll
    for (int i = 0; i < 32; i += 8)
        tile[y + i][x] = src[(size_t)(r0 + y + i) * C + c0 + x];
    __syncthreads();
    #pragma unroll
    for (int i = 0; i < 32; i += 8)
        dst[(size_t)(c0 + y + i) * R + r0 + x] = __float2half_rn(tile[x][y + i]);
}

// ============================ transpose V (fp16) ===========================
__global__ void transpose_v_kernel() {
    __shared__ __half tile[32][33];
    int z = blockIdx.z;
    const __half* src = g_v + (size_t)z * S_ * DH_;
    __half* dst = g_vT + (size_t)z * S_ * DH_;
    int s0 = blockIdx.y * 32, d0 = blockIdx.x * 32;
    int x = threadIdx.x, y = threadIdx.y;
    #pragma unroll
    for (int i = 0; i < 32; i += 8)
        tile[y + i][x] = src[(size_t)(s0 + y + i) * DH_ + d0 + x];
    __syncthreads();
    #pragma unroll
    for (int i = 0; i < 32; i += 8)
        dst[(size_t)(d0 + y + i) * S_ + s0 + x] = tile[x][y + i];
}

// ============================ gated expand (O), fp16 out ===================
__global__ __launch_bounds__(256) void expand_kernel() {
    int idx = blockIdx.x * 256 + threadIdx.x;
    int dh4 = idx & 31;
    int he = (idx >> 5) & 31;
    int t = idx >> 10;
    int h = he >> 2;
    int b = t >> 11, s = t & (S_ - 1);
    float g = g_go[(size_t)t * GE_ + he];
    float4 r = *(const float4*)&g_res[(((size_t)b * H_ + h) * S_ + s) * DH_ + dh4 * 4];
    __half2* dst = (__half2*)&g_aexp[(size_t)t * KEXP_ + he * 128 + dh4 * 4];
    dst[0] = __floats2half2_rn(r.x * g, r.y * g);
    dst[1] = __floats2half2_rn(r.z * g, r.w * g);
}

// ============================ gated reduce (V), fp16 in/out ================
__global__ __launch_bounds__(256) void vgate_kernel() {
    int idx = blockIdx.x * 256 + threadIdx.x;
    int dh4 = idx & 31;
    int h = (idx >> 5) & 7;
    int t = idx >> 8;
    int b = t >> 11, s = t & (S_ - 1);
    const __half2* y = (const __half2*)(g_yall + (size_t)t * KEXP_ + h * 512) + dh4 * 2;
    const float* g = g_gv + (size_t)t * GE_ + h * 4;
    float2 a0 = make_float2(0.f, 0.f), a1 = make_float2(0.f, 0.f);
    #pragma unroll
    for (int e = 0; e < 4; e++) {
        float ge = g[e];
        float2 y0 = __half22float2(y[e * 64 + 0]);
        float2 y1 = __half22float2(y[e * 64 + 1]);
        a0.x += ge * y0.x; a0.y += ge * y0.y;
        a1.x += ge * y1.x; a1.y += ge * y1.y;
    }
    __half2* dst = (__half2*)&g_v[(((size_t)b * H_ + h) * S_ + s) * DH_ + dh4 * 4];
    dst[0] = __floats2half2_rn(a0.x, a0.y);
    dst[1] = __floats2half2_rn(a1.x, a1.y);
}

// ============================ fp16 mma GEMM (cp.async + ldmatrix) ==========
// MODE 0: fp32 row-major C.  MODE 1: qk merged, fp16 C [B,H,S,DH].
// MODE 2: fp16 row-major C.
#define PADH_ 36
#define ABUF_ (128 * PADH_)
#define BBUF_ (256 * PADH_)
#define STG_W (ABUF_ + BBUF_)
#define GSMEM_BYTES (3 * STG_W * 4)     // 165888

template<int MODE>
__global__ __launch_bounds__(512) void gemm_f16(const __half* __restrict__ A,
                                                const __half* __restrict__ B,
                                                void* __restrict__ Cv,
                                                int Ktot, int ldc, float alpha,
                                                const __half* __restrict__ A2,
                                                const __half* __restrict__ B2,
                                                void* __restrict__ C2v) {
    extern __shared__ __align__(16) uint32_t dsm[];
    uint32_t sbase = smem_u32(dsm);

    int tid = threadIdx.x;
    int wid = tid >> 5;
    int lane = tid & 31;
    int m0 = blockIdx.y * 128, n0 = blockIdx.x * 256;
    int m0w = (wid >> 2) * 32, n0w = (wid & 3) * 64;

    void* Cp = Cv;
    if (MODE == 1 && blockIdx.z == 1) { A = A2; B = B2; Cp = C2v; }

    int ar0 = tid >> 3, ao0 = (tid & 7) * 8;
    int aS1 = tid + 512;
    int ar1 = aS1 >> 3, ao1 = (aS1 & 7) * 8;
    const __half* Asrc0 = A + (size_t)(m0 + ar0) * Ktot + ao0;
    const __half* Asrc1 = A + (size_t)(m0 + ar1) * Ktot + ao1;
    uint32_t aDst0 = (uint32_t)(ar0 * PADH_ + (ao0 >> 1)) * 4;
    uint32_t aDst1 = (uint32_t)(ar1 * PADH_ + (ao1 >> 1)) * 4;
    const __half* Bsrc[4];
    uint32_t bDst[4];
    #pragma unroll
    for (int j = 0; j < 4; j++) {
        int s = tid + 512 * j;
        int brr = s >> 3, bo = (s & 7) * 8;
        Bsrc[j] = B + (size_t)(n0 + brr) * Ktot + bo;
        bDst[j] = (uint32_t)(ABUF_ + brr * PADH_ + (bo >> 1)) * 4;
    }

    float acc[2][8][4];
    #pragma unroll
    for (int i = 0; i < 2; i++)
        #pragma unroll
        for (int j = 0; j < 8; j++)
            #pragma unroll
            for (int c = 0; c < 4; c++) acc[i][j][c] = 0.f;

    int KT = Ktot >> 6;

    auto copyTile = [&](int kt, int stg) {
        uint32_t so = sbase + (uint32_t)(stg * STG_W * 4);
        int ko = kt * 64;
        CP16(so + aDst0, Asrc0 + ko);
        CP16(so + aDst1, Asrc1 + ko);
        #pragma unroll
        for (int j = 0; j < 4; j++)
            CP16(so + bDst[j], Bsrc[j] + ko);
        CP_COMMIT();
    };

    copyTile(0, 0);
    copyTile(1, 1);

    // ldmatrix per-thread row/col offsets
    int g8 = lane >> 3, l8 = lane & 7;
    // A x4: m0:(rows lr,k lo) m1:(lr+8,k lo) m2:(lr,k hi) m3:(lr+8,k hi)
    uint32_t aRow = (uint32_t)(m0w + (g8 & 1) * 8 + l8);
    uint32_t aCo  = (uint32_t)((g8 >> 1) * 4);
    // B x4 pair p: m0:(rows p16+lr,k lo) m1:(same,k hi) m2:(rows+8,k lo) m3:(+8,k hi)
    uint32_t bRow = (uint32_t)(n0w + (g8 >> 1) * 8 + l8);
    uint32_t bCo  = (uint32_t)((g8 & 1) * 4);

    for (int kt = 0; kt < KT; kt++) {
        if (kt + 1 < KT) CP_WAIT1(); else CP_WAIT0();
        __syncthreads();

        uint32_t AsAddr = sbase + (uint32_t)((kt % 3) * STG_W * 4);
        uint32_t BsAddr = AsAddr + (uint32_t)(ABUF_ * 4);
        #pragma unroll
        for (int ks = 0; ks < 4; ks++) {
            uint32_t kb = (uint32_t)(ks * 8);
            uint32_t a[2][4], b[8][2];
            #pragma unroll
            for (int mi = 0; mi < 2; mi++)
                ldsm4(AsAddr + ((aRow + mi * 16) * PADH_ + kb + aCo) * 4, a[mi]);
            #pragma unroll
            for (int p = 0; p < 4; p++) {
                uint32_t r4v[4];
                ldsm4(BsAddr + ((bRow + p * 16) * PADH_ + kb + bCo) * 4, r4v);
                b[2 * p][0] = r4v[0]; b[2 * p][1] = r4v[1];
                b[2 * p + 1][0] = r4v[2]; b[2 * p + 1][1] = r4v[3];
            }
            #pragma unroll
            for (int mi = 0; mi < 2; mi++)
                #pragma unroll
                for (int ni = 0; ni < 8; ni++)
                    mma_f16(acc[mi][ni], a[mi], b[ni]);
        }

        if (kt + 2 < KT) copyTile(kt + 2, (kt + 2) % 3);
    }

    int r4 = lane >> 2, c4 = lane & 3;
    #pragma unroll
    for (int mi = 0; mi < 2; mi++) {
        #pragma unroll
        for (int half_m = 0; half_m < 2; half_m++) {
            int m = m0 + m0w + mi * 16 + half_m * 8 + r4;
            int bb = m >> 11, ss = m & (S_ - 1);
            #pragma unroll
            for (int ni = 0; ni < 8; ni++) {
                int n = n0 + n0w + ni * 8 + c4 * 2;
                float ox = acc[mi][ni][half_m * 2 + 0] * alpha;
                float oy = acc[mi][ni][half_m * 2 + 1] * alpha;
                if (MODE == 1) {
                    int h = n >> 7, dh = n & 127;
                    *(__half2*)((__half*)Cp + (((size_t)bb * H_ + h) * S_ + ss) * DH_ + dh) =
                        __floats2half2_rn(ox, oy);
                } else if (MODE == 2) {
                    *(__half2*)((__half*)Cp + (size_t)m * ldc + n) = __floats2half2_rn(ox, oy);
                } else {
                    *(float2*)((float*)Cp + (size_t)m * ldc + n) = make_float2(ox, oy);
                }
            }
        }
    }
}

// ============================ fp16 flash attention (ldmatrix) ==============
#define APH_ 68
#define ATILE_ (128 * APH_)
#define QS_OFF 0
#define KS_OFF ATILE_
#define VT_OFF (3 * ATILE_)
#define PS_OFF (5 * ATILE_)
#define ATTN_SMEM (6 * ATILE_ * 4)      // 208896

__global__ __launch_bounds__(256) void attn_tc_kernel() {
    extern __shared__ __align__(16) uint32_t asm_[];
    uint32_t sbase = smem_u32(asm_);
    uint32_t* Qs = asm_ + QS_OFF;
    uint32_t* Ps = asm_ + PS_OFF;
    uint32_t QsAddr = sbase;
    uint32_t PsAddr = sbase + (uint32_t)(PS_OFF * 4);

    int bh = blockIdx.y;
    int q0 = blockIdx.x * 128;
    const __half* Qg = g_q + (size_t)bh * S_ * DH_;
    const __half* Kg = g_k + (size_t)bh * S_ * DH_;
    const __half* VTg = g_vT + (size_t)bh * S_ * DH_;

    int tid = threadIdx.x;
    int wid = tid >> 5;
    int lane = tid & 31;
    int r4 = lane >> 2, c4 = lane & 3;
    int m0w = wid * 16;
    int g8 = lane >> 3, l8 = lane & 7;
    uint32_t aRow = (uint32_t)(m0w + (g8 & 1) * 8 + l8);
    uint32_t aCo  = (uint32_t)((g8 >> 1) * 4);
    uint32_t bRow = (uint32_t)((g8 >> 1) * 8 + l8);
    uint32_t bCo  = (uint32_t)((g8 & 1) * 4);

    for (int i = tid; i < 2048; i += 256) {
        int r = i >> 4, w = i & 15;
        *(uint4*)&Qs[r * APH_ + w * 4] = *(const uint4*)(Qg + (size_t)(q0 + r) * DH_ + w * 8);
    }

    auto copyKV = [&](int j0, int buf) {
        uint32_t ks = sbase + (uint32_t)((KS_OFF + buf * ATILE_) * 4);
        uint32_t vs = sbase + (uint32_t)((VT_OFF + buf * ATILE_) * 4);
        #pragma unroll
        for (int jj = 0; jj < 8; jj++) {
            int i = tid + 256 * jj;
            int r = i >> 4, w = i & 15;
            CP16(ks + (uint32_t)(r * APH_ + w * 4) * 4, Kg + (size_t)(j0 + r) * DH_ + w * 8);
            CP16(vs + (uint32_t)(r * APH_ + w * 4) * 4, VTg + (size_t)r * S_ + j0 + w * 8);
        }
        CP_COMMIT();
    };

    copyKV(0, 0);

    float o[16][4];
    #pragma unroll
    for (int ni = 0; ni < 16; ni++)
        #pragma unroll
        for (int c = 0; c < 4; c++) o[ni][c] = 0.f;
    float mA = -1e30f, mB = -1e30f, lA = 0.f, lB = 0.f;

    for (int it = 0; it < S_ / 128; it++) {
        int buf = it & 1;
        __syncthreads();
        if (it + 1 < S_ / 128) {
            copyKV((it + 1) * 128, buf ^ 1);
            CP_WAIT1();
        } else {
            CP_WAIT0();
        }
        __syncthreads();

        uint32_t KsAddr = sbase + (uint32_t)((KS_OFF + buf * ATILE_) * 4);
        uint32_t VtAddr = sbase + (uint32_t)((VT_OFF + buf * ATILE_) * 4);

        float sf[16][4];
        #pragma unroll
        for (int ni = 0; ni < 16; ni++)
            #pragma unroll
            for (int c = 0; c < 4; c++) sf[ni][c] = 0.f;

        #pragma unroll
        for (int ks = 0; ks < 8; ks++) {
            uint32_t kb = (uint32_t)(ks * 8);
            uint32_t a[4], b[16][2];
            ldsm4(QsAddr + (aRow * APH_ + kb + aCo) * 4, a);
            #pragma unroll
            for (int p = 0; p < 8; p++) {
                uint32_t r4v[4];
                ldsm4(KsAddr + ((bRow + p * 16) * APH_ + kb + bCo) * 4, r4v);
                b[2 * p][0] = r4v[0]; b[2 * p][1] = r4v[1];
                b[2 * p + 1][0] = r4v[2]; b[2 * p + 1][1] = r4v[3];
            }
            #pragma unroll
            for (int ni = 0; ni < 16; ni++)
                mma_f16(sf[ni], a, b[ni]);
        }

        float mxA = -1e30f, mxB = -1e30f;
        #pragma unroll
        for (int ni = 0; ni < 16; ni++) {
            mxA = fmaxf(mxA, fmaxf(sf[ni][0], sf[ni][1]));
            mxB = fmaxf(mxB, fmaxf(sf[ni][2], sf[ni][3]));
        }
        mxA = fmaxf(mxA, __shfl_xor_sync(0xffffffffu, mxA, 1));
        mxA = fmaxf(mxA, __shfl_xor_sync(0xffffffffu, mxA, 2));
        mxB = fmaxf(mxB, __shfl_xor_sync(0xffffffffu, mxB, 1));
        mxB = fmaxf(mxB, __shfl_xor_sync(0xffffffffu, mxB, 2));
        float mnA = fmaxf(mA, mxA), mnB = fmaxf(mB, mxB);
        float scA = __expf(mA - mnA), scB = __expf(mB - mnB);
        float sA = 0.f, sB = 0.f;
        int prA = (m0w + r4) * APH_;
        int prB = prA + 8 * APH_;
        #pragma unroll
        for (int ni = 0; ni < 16; ni++) {
            float e0 = __expf(sf[ni][0] - mnA);
            float e1 = __expf(sf[ni][1] - mnA);
            float e2 = __expf(sf[ni][2] - mnB);
            float e3 = __expf(sf[ni][3] - mnB);
            sA += e0 + e1; sB += e2 + e3;
            int cw = ni * 4 + c4;
            Ps[prA + cw] = pack_h2(e0, e1);
            Ps[prB + cw] = pack_h2(e2, e3);
        }
        sA += __shfl_xor_sync(0xffffffffu, sA, 1);
        sA += __shfl_xor_sync(0xffffffffu, sA, 2);
        sB += __shfl_xor_sync(0xffffffffu, sB, 1);
        sB += __shfl_xor_sync(0xffffffffu, sB, 2);
        lA = lA * scA + sA; lB = lB * scB + sB;
        mA = mnA; mB = mnB;
        #pragma unroll
        for (int ni = 0; ni < 16; ni++) {
            o[ni][0] *= scA; o[ni][1] *= scA;
            o[ni][2] *= scB; o[ni][3] *= scB;
        }
        __syncwarp();

        #pragma unroll
        for (int ks = 0; ks < 8; ks++) {
            uint32_t kb = (uint32_t)(ks * 8);
            uint32_t a[4], b[16][2];
            ldsm4(PsAddr + (aRow * APH_ + kb + aCo) * 4, a);
            #pragma unroll
            for (int p = 0; p < 8; p++) {
                uint32_t r4v[4];
                ldsm4(VtAddr + ((bRow + p * 16) * APH_ + kb + bCo) * 4, r4v);
                b[2 * p][0] = r4v[0]; b[2 * p][1] = r4v[1];
                b[2 * p + 1][0] = r4v[2]; b[2 * p + 1][1] = r4v[3];
            }
            #pragma unroll
            for (int ni = 0; ni < 16; ni++)
                mma_f16(o[ni], a, b[ni]);
        }
    }

    float invA = 1.f / lA, invB = 1.f / lB;
    int rA = q0 + m0w + r4;
    float* OgA = g_res + (size_t)bh * S_ * DH_ + (size_t)rA * DH_;
    float* OgB = OgA + 8 * DH_;
    #pragma unroll
    for (int ni = 0; ni < 16; ni++) {
        int cc = ni * 8 + c4 * 2;
        float2 oa, ob;
        oa.x = o[ni][0] * invA; oa.y = o[ni][1] * invA;
        ob.x = o[ni][2] * invB; ob.y = o[ni][3] * invB;
        *(float2*)(OgA + cc) = oa;
        *(float2*)(OgB + cc) = ob;
    }
}

// ---------------------------------------------------------------------------
extern "C" void kernel_launch(void* const* d_in, const int* in_sizes, int n_in,
                              void* d_out, int out_size) {
    const float* q_src = (const float*)d_in[0];
    const float* k_src = (const float*)d_in[1];
    const float* v_src = (const float*)d_in[2];
    const float* Wq    = (const float*)d_in[3];
    const float* Wk    = (const float*)d_in[4];
    const float* Wv    = (const float*)d_in[5];
    const float* Wo    = (const float*)d_in[6];
    const float* sel_v = (const float*)d_in[7];
    const float* sel_o = (const float*)d_in[8];
    float* outp = (float*)d_out;

    cudaFuncSetAttribute(attn_tc_kernel, cudaFuncAttributeMaxDynamicSharedMemorySize, ATTN_SMEM);
    cudaFuncSetAttribute(gemm_f16<0>, cudaFuncAttributeMaxDynamicSharedMemorySize, GSMEM_BYTES);
    cudaFuncSetAttribute(gemm_f16<1>, cudaFuncAttributeMaxDynamicSharedMemorySize, GSMEM_BYTES);
    cudaFuncSetAttribute(gemm_f16<2>, cudaFuncAttributeMaxDynamicSharedMemorySize, GSMEM_BYTES);
    cudaFuncSetAttribute(router_kernel, cudaFuncAttributeMaxDynamicSharedMemorySize, RSMEM_BYTES);

    __half *gq, *gk, *gyall, *gaexp, *gwvT, *gwoT, *gqc, *gkc, *gvc, *gwqc, *gwkc;
    cudaGetSymbolAddress((void**)&gq, g_q);
    cudaGetSymbolAddress((void**)&gk, g_k);
    cudaGetSymbolAddress((void**)&gyall, g_yall);
    cudaGetSymbolAddress((void**)&gaexp, g_aexp);
    cudaGetSymbolAddress((void**)&gwvT, g_wvT);
    cudaGetSymbolAddress((void**)&gwoT, g_woT);
    cudaGetSymbolAddress((void**)&gqc, g_qc);
    cudaGetSymbolAddress((void**)&gkc, g_kc);
    cudaGetSymbolAddress((void**)&gvc, g_vc);
    cudaGetSymbolAddress((void**)&gwqc, g_wqc);
    cudaGetSymbolAddress((void**)&gwkc, g_wkc);

    const float scale = 0.29730177875068026f;  // 128^-0.25

    router_kernel<<<dim3(TOK_ / RT_, 2), 256, RSMEM_BYTES>>>(k_src, q_src, sel_v, sel_o);

    int n4a = TOK_ * D_ / 4, n4w = D_ * D_ / 4;
    conv_kernel<<<(n4a + 255) / 256, 256>>>(q_src, gqc, n4a);
    conv_kernel<<<(n4a + 255) / 256, 256>>>(k_src, gkc, n4a);
    conv_kernel<<<(n4a + 255) / 256, 256>>>(v_src, gvc, n4a);
    conv_kernel<<<(n4w + 255) / 256, 256>>>(Wq, gwqc, n4w);
    conv_kernel<<<(n4w + 255) / 256, 256>>>(Wk, gwkc, n4w);

    transpose_kernel<<<dim3(DH_ / 32, D_ / 32, GE_), dim3(32, 8)>>>(Wv, gwvT, D_, DH_);
    transpose_kernel<<<dim3(D_ / 32, KEXP_ / 32, 1), dim3(32, 8)>>>(Wo, gwoT, KEXP_, D_);

    // merged q/k projections: M=4096, N=1024, K=1024; z=0 -> q, z=1 -> k
    gemm_f16<1><<<dim3(D_ / 256, TOK_ / 128, 2), 512, GSMEM_BYTES>>>(
        gqc, gwqc, gq, D_, 0, scale, gkc, gwkc, gk);

    // all-expert V: M=4096, N=4096, K=1024 -> fp16 yall
    gemm_f16<2><<<dim3(KEXP_ / 256, TOK_ / 128), 512, GSMEM_BYTES>>>(
        gvc, gwvT, gyall, D_, KEXP_, 1.0f, nullptr, nullptr, nullptr);
    vgate_kernel<<<TOK_ * H_ * 32 / 256, 256>>>();
    transpose_v_kernel<<<dim3(DH_ / 32, S_ / 32, B_ * H_), dim3(32, 8)>>>();

    attn_tc_kernel<<<dim3(S_ / 128, B_ * H_), 256, ATTN_SMEM>>>();

    expand_kernel<<<TOK_ * GE_ * 32 / 256, 256>>>();
    // out: M=4096, N=1024, K=4096 -> fp32
    gemm_f16<0><<<dim3(D_ / 256, TOK_ / 128), 512, GSMEM_BYTES>>>(
        gaexp, gwoT, outp, KEXP_, D_, 1.0f, nullptr, nullptr, nullptr);
}